// round 7
// baseline (speedup 1.0000x reference)
#include <cuda_runtime.h>
#include <math.h>
#include <stdint.h>

#define N_USERS 100000
#define N_ITEMS 50000
#define DD      64
#define NE      2000000
#define CAT_RATE 0.55f

#define NBU 98          // ceil(100000/1024)
#define NBI 49          // ceil(50000/1024)
#define GB  391         // ceil(50000/128) gemm blocks per matrix
#define SBU 12500       // 100000 rows / 8 warps
#define SBI 6250        // 50000 rows / 8 warps
#define APB 1024        // apply_norm grid-stride blocks
#define HB  2048        // hist blocks
#define NSB 1024        // norm_stats blocks
#define SCB 2048        // scatter blocks

// ------------------------- static device scratch (no allocs) -------------------------
__device__ float g_imgfeat[(size_t)N_ITEMS * DD];
__device__ float g_txtfeat[(size_t)N_ITEMS * DD];
__device__ float g_ug[(size_t)N_USERS * DD];
__device__ float g_uacc[(size_t)N_USERS * DD];
__device__ float g_ig[(size_t)N_ITEMS * DD];
__device__ float g_iacc[(size_t)N_ITEMS * DD];

__device__ int   g_ucnt[N_USERS];
__device__ int   g_icnt[N_ITEMS];
__device__ int   g_urp[N_USERS + 1];
__device__ int   g_irp[N_ITEMS + 1];
__device__ int   g_ucur[N_USERS];
__device__ int   g_icur[N_ITEMS];
__device__ int   g_ucol[NE];
__device__ float g_uval[NE];
__device__ int   g_icol[NE];
__device__ float g_ival[NE];
__device__ int   g_upart[128];
__device__ int   g_ipart[128];
__device__ float g_stats[66];   // [0..63] col means, [64] inv rownorm

// ======================= device role functions =======================

__device__ __forceinline__ void dev_hist(const int* __restrict__ eu,
                                         const int* __restrict__ ei,
                                         int bid, int nb) {
    int i = bid * 256 + threadIdx.x;
    int stride = nb * 256;
    for (; i < NE; i += stride) {
        atomicAdd(&g_ucnt[eu[i]], 1);
        atomicAdd(&g_icnt[ei[i]], 1);
    }
}

__device__ void dev_norm_stats(const float* __restrict__ ue,
                               const float* __restrict__ ie,
                               int bid, int nb) {
    int t = threadIdx.x;           // 256
    int c = t & 63;
    int rsub = t >> 6;             // 0..3
    float s = 0.f, q = 0.f;
    for (int r = bid * 4 + rsub; r < N_USERS + N_ITEMS; r += nb * 4) {
        const float* src = (r < N_USERS) ? (ue + (size_t)r * 64)
                                         : (ie + (size_t)(r - N_USERS) * 64);
        float v = src[c];
        s += v; q += v * v;
    }
    __shared__ float scol[256], sq[256];
    scol[t] = s; sq[t] = q;
    __syncthreads();
    for (int st = 128; st > 0; st >>= 1) { if (t < st) sq[t] += sq[t + st]; __syncthreads(); }
    if (t < 64) {
        float cs = scol[t] + scol[t + 64] + scol[t + 128] + scol[t + 192];
        atomicAdd(&g_stats[t], cs);
    }
    if (t == 0) atomicAdd(&g_stats[64], sq[0]);
}

// ---------------- tf32 tensor-core GEMM: out[M,64] = A[M,K] @ W[K,64] + b -----------
__device__ __forceinline__ uint32_t f2tf32(float f) {
    uint32_t u;
    asm("cvt.rna.tf32.f32 %0, %1;" : "=r"(u) : "f"(f));
    return u;
}

#define WS_STRIDE 76    // floats per row (padded, float4-aligned, conflict-spread)

__device__ void dev_gemm_tf32(const float* __restrict__ A,
                              const float* __restrict__ W,
                              const float* __restrict__ bias,
                              float* __restrict__ out, int M, int K, int bid,
                              float* Ws /* [64*WS_STRIDE] smem */) {
    int tid  = threadIdx.x;
    int warp = tid >> 5, lane = tid & 31;
    int gid  = lane >> 2, tid4 = lane & 3;
    int rA = bid * 128 + warp * 16 + gid;
    int rB = rA + 8;
    bool okA = rA < M, okB = rB < M;
    const float* ArA = A + (size_t)rA * K;
    const float* ArB = A + (size_t)rB * K;

    float c[8][4];
    #pragma unroll
    for (int t = 0; t < 8; ++t) { c[t][0]=0.f; c[t][1]=0.f; c[t][2]=0.f; c[t][3]=0.f; }

    for (int k0 = 0; k0 < K; k0 += 64) {
        #pragma unroll
        for (int i = 0; i < 4; ++i) {
            int li = tid + i * 256;
            int r = li >> 4;
            int cb = (li & 15) * 4;
            float4 w = *(const float4*)(W + (size_t)(k0 + r) * 64 + cb);
            float* wr = Ws + r * WS_STRIDE;
            wr[((cb + 0) & 7) * 8 + ((cb + 0) >> 3)] = __uint_as_float(f2tf32(w.x));
            wr[((cb + 1) & 7) * 8 + ((cb + 1) >> 3)] = __uint_as_float(f2tf32(w.y));
            wr[((cb + 2) & 7) * 8 + ((cb + 2) >> 3)] = __uint_as_float(f2tf32(w.z));
            wr[((cb + 3) & 7) * 8 + ((cb + 3) >> 3)] = __uint_as_float(f2tf32(w.w));
        }
        __syncthreads();
        #pragma unroll
        for (int ks = 0; ks < 8; ++ks) {
            int kk = k0 + ks * 8;
            float a0 = 0.f, a1 = 0.f, a2 = 0.f, a3 = 0.f;
            if (okA) { a0 = ArA[kk + tid4]; a2 = ArA[kk + tid4 + 4]; }
            if (okB) { a1 = ArB[kk + tid4]; a3 = ArB[kk + tid4 + 4]; }
            uint32_t ua0 = f2tf32(a0), ua1 = f2tf32(a1);
            uint32_t ua2 = f2tf32(a2), ua3 = f2tf32(a3);
            const float* w0 = Ws + (ks * 8 + tid4) * WS_STRIDE + gid * 8;
            const float* w1 = Ws + (ks * 8 + tid4 + 4) * WS_STRIDE + gid * 8;
            float b0arr[8], b1arr[8];
            *(float4*)&b0arr[0] = *(const float4*)(w0);
            *(float4*)&b0arr[4] = *(const float4*)(w0 + 4);
            *(float4*)&b1arr[0] = *(const float4*)(w1);
            *(float4*)&b1arr[4] = *(const float4*)(w1 + 4);
            #pragma unroll
            for (int t = 0; t < 8; ++t) {
                uint32_t ub0 = __float_as_uint(b0arr[t]);
                uint32_t ub1 = __float_as_uint(b1arr[t]);
                asm volatile(
                    "mma.sync.aligned.m16n8k8.row.col.f32.tf32.tf32.f32 "
                    "{%0,%1,%2,%3}, {%4,%5,%6,%7}, {%8,%9}, {%0,%1,%2,%3};"
                    : "+f"(c[t][0]), "+f"(c[t][1]), "+f"(c[t][2]), "+f"(c[t][3])
                    : "r"(ua0), "r"(ua1), "r"(ua2), "r"(ua3), "r"(ub0), "r"(ub1));
            }
        }
        __syncthreads();
    }
    #pragma unroll
    for (int t = 0; t < 8; ++t) {
        int n = t * 8 + 2 * tid4;
        float bx = bias[n], by = bias[n + 1];
        if (okA) *(float2*)(out + (size_t)rA * 64 + n) = make_float2(c[t][0] + bx, c[t][1] + by);
        if (okB) *(float2*)(out + (size_t)rB * 64 + n) = make_float2(c[t][2] + bx, c[t][3] + by);
    }
}

// ---------------- CSR scan helpers ----------------
__device__ void dev_block_sums(const int* __restrict__ cnt, int n,
                               int* __restrict__ part, int bid) {
    __shared__ int sm[256];
    int t = threadIdx.x;
    int base = bid * 1024;
    int s = 0;
    #pragma unroll
    for (int r = 0; r < 4; ++r) {
        int idx = base + t * 4 + r;
        if (idx < n) s += cnt[idx];
    }
    sm[t] = s; __syncthreads();
    for (int st = 128; st > 0; st >>= 1) { if (t < st) sm[t] += sm[t + st]; __syncthreads(); }
    if (t == 0) part[bid] = sm[0];
}

__device__ void dev_norm_finalize() {
    __shared__ float smf[64];
    int t = threadIdx.x;
    if (t < 64) {
        float n = (float)(N_USERS + N_ITEMS);
        float mean = g_stats[t] / n;
        smf[t] = mean * mean;
    }
    __syncthreads();
    if (t == 0) {
        float ssum = 0.f;
        #pragma unroll
        for (int i = 0; i < 64; ++i) ssum += smf[i];
        float n = (float)(N_USERS + N_ITEMS);
        float Q = g_stats[64];
        smf[0] = rsqrtf(Q / n - ssum + 1e-6f);
    }
    __syncthreads();
    if (t < 64) g_stats[t] = g_stats[t] / (float)(N_USERS + N_ITEMS);
    __syncthreads();
    if (t == 0) g_stats[64] = smf[0];
}

__device__ void dev_scan_small(int* __restrict__ part, int n) {
    __shared__ int sm[128];
    int t = threadIdx.x;   // 128 threads
    int v = (t < n) ? part[t] : 0;
    sm[t] = v; __syncthreads();
    for (int off = 1; off < 128; off <<= 1) {
        int x = (t >= off) ? sm[t - off] : 0;
        __syncthreads();
        sm[t] += x;
        __syncthreads();
    }
    part[t] = sm[t] - v;   // exclusive
}

__device__ void dev_scan_chunks(const int* __restrict__ cnt, int n,
                                const int* __restrict__ part,
                                int* __restrict__ rp, int* __restrict__ cur, int bid) {
    __shared__ int sm[256];
    int t = threadIdx.x;
    int base = bid * 1024;
    int v[4]; int local = 0;
    #pragma unroll
    for (int r = 0; r < 4; ++r) {
        int idx = base + t * 4 + r;
        v[r] = (idx < n) ? cnt[idx] : 0;
        local += v[r];
    }
    sm[t] = local; __syncthreads();
    for (int off = 1; off < 256; off <<= 1) {
        int x = (t >= off) ? sm[t - off] : 0;
        __syncthreads();
        sm[t] += x;
        __syncthreads();
    }
    int excl = sm[t] - local + part[bid];
    #pragma unroll
    for (int r = 0; r < 4; ++r) {
        int idx = base + t * 4 + r;
        if (idx < n) { rp[idx] = excl; cur[idx] = excl; }
        excl += v[r];
    }
}

__device__ void dev_apply_norm(const float* __restrict__ ue,
                               const float* __restrict__ ie, int bid, int nb) {
    float inv = g_stats[64];
    int idx = bid * 256 + threadIdx.x;
    int stride = nb * 256;
    const int NU = N_USERS * 64;
    const int NT = (N_USERS + N_ITEMS) * 64;
    for (; idx < NT; idx += stride) {
        int c = idx & 63;
        if (idx < NU) {
            float v = (ue[idx] - g_stats[c]) * inv;
            g_ug[idx] = v; g_uacc[idx] = v;
        } else {
            int j = idx - NU;
            float v = (ie[j] - g_stats[c]) * inv;
            g_ig[j] = v; g_iacc[j] = v;
        }
    }
}

__device__ void dev_scatter(const int* __restrict__ eu, const int* __restrict__ ei,
                            const float* __restrict__ vui, const float* __restrict__ viu,
                            int bid, int nb) {
    int i = bid * 256 + threadIdx.x;
    int stride = nb * 256;
    for (; i < NE; i += stride) {
        int u = eu[i], it = ei[i];
        int p = atomicAdd(&g_ucur[u], 1);
        g_ucol[p] = it; g_uval[p] = vui[i];
        int q = atomicAdd(&g_icur[it], 1);
        g_icol[q] = u; g_ival[q] = viu[i];
    }
}

// ---------------- SpMM (warp/row; half-warps process alternating edges, lane4 = float4) ----
__device__ __forceinline__ void dev_spmm(const int* __restrict__ rp,
                                         const int* __restrict__ cols,
                                         const float* __restrict__ vals,
                                         const float* __restrict__ src,
                                         float* __restrict__ out,
                                         float* __restrict__ acc,
                                         int n_rows, int bid) {
    int row = bid * 8 + ((int)threadIdx.x >> 5);
    if (row >= n_rows) return;
    int lane = threadIdx.x & 31;
    int half = lane >> 4;        // 0 or 1
    int l16  = lane & 15;        // col group: 4 floats
    int s = rp[row], e = rp[row + 1];
    float4 a4 = make_float4(0.f, 0.f, 0.f, 0.f);
    for (int j = s + half; j < e; j += 2) {
        float v = __ldg(&vals[j]);
        int c = __ldg(&cols[j]);
        float4 sv = *(const float4*)(src + (size_t)c * 64 + l16 * 4);
        a4.x = fmaf(v, sv.x, a4.x); a4.y = fmaf(v, sv.y, a4.y);
        a4.z = fmaf(v, sv.z, a4.z); a4.w = fmaf(v, sv.w, a4.w);
    }
    __syncwarp();
    a4.x += __shfl_xor_sync(0xFFFFFFFFu, a4.x, 16);
    a4.y += __shfl_xor_sync(0xFFFFFFFFu, a4.y, 16);
    a4.z += __shfl_xor_sync(0xFFFFFFFFu, a4.z, 16);
    a4.w += __shfl_xor_sync(0xFFFFFFFFu, a4.w, 16);
    if (half == 0) {
        size_t base = (size_t)row * 64 + l16 * 4;
        *(float4*)(out + base) = a4;
        if (acc) {
            float4* ap = (float4*)(acc + base);
            float4 t = *ap;
            t.x += a4.x; t.y += a4.y; t.z += a4.z; t.w += a4.w;
            *ap = t;
        }
    }
}

// triple-source: same CSR, three feature tables, acc on third output
__device__ __forceinline__ void dev_spmm3(const int* __restrict__ rp,
                                          const int* __restrict__ cols,
                                          const float* __restrict__ vals,
                                          const float* __restrict__ sA,
                                          const float* __restrict__ sB,
                                          const float* __restrict__ sC,
                                          float* __restrict__ oA,
                                          float* __restrict__ oB,
                                          float* __restrict__ oC,
                                          float* __restrict__ acc,
                                          int n_rows, int bid) {
    int row = bid * 8 + ((int)threadIdx.x >> 5);
    if (row >= n_rows) return;
    int lane = threadIdx.x & 31;
    int half = lane >> 4;
    int l16  = lane & 15;
    int s = rp[row], e = rp[row + 1];
    float4 aA = make_float4(0.f,0.f,0.f,0.f);
    float4 aB = aA, aC = aA;
    for (int j = s + half; j < e; j += 2) {
        float v = __ldg(&vals[j]);
        int c = __ldg(&cols[j]);
        size_t o = (size_t)c * 64 + l16 * 4;
        float4 x = *(const float4*)(sA + o);
        float4 y = *(const float4*)(sB + o);
        float4 z = *(const float4*)(sC + o);
        aA.x = fmaf(v, x.x, aA.x); aA.y = fmaf(v, x.y, aA.y);
        aA.z = fmaf(v, x.z, aA.z); aA.w = fmaf(v, x.w, aA.w);
        aB.x = fmaf(v, y.x, aB.x); aB.y = fmaf(v, y.y, aB.y);
        aB.z = fmaf(v, y.z, aB.z); aB.w = fmaf(v, y.w, aB.w);
        aC.x = fmaf(v, z.x, aC.x); aC.y = fmaf(v, z.y, aC.y);
        aC.z = fmaf(v, z.z, aC.z); aC.w = fmaf(v, z.w, aC.w);
    }
    __syncwarp();
    aA.x += __shfl_xor_sync(0xFFFFFFFFu, aA.x, 16);
    aA.y += __shfl_xor_sync(0xFFFFFFFFu, aA.y, 16);
    aA.z += __shfl_xor_sync(0xFFFFFFFFu, aA.z, 16);
    aA.w += __shfl_xor_sync(0xFFFFFFFFu, aA.w, 16);
    aB.x += __shfl_xor_sync(0xFFFFFFFFu, aB.x, 16);
    aB.y += __shfl_xor_sync(0xFFFFFFFFu, aB.y, 16);
    aB.z += __shfl_xor_sync(0xFFFFFFFFu, aB.z, 16);
    aB.w += __shfl_xor_sync(0xFFFFFFFFu, aB.w, 16);
    aC.x += __shfl_xor_sync(0xFFFFFFFFu, aC.x, 16);
    aC.y += __shfl_xor_sync(0xFFFFFFFFu, aC.y, 16);
    aC.z += __shfl_xor_sync(0xFFFFFFFFu, aC.z, 16);
    aC.w += __shfl_xor_sync(0xFFFFFFFFu, aC.w, 16);
    if (half == 0) {
        size_t base = (size_t)row * 64 + l16 * 4;
        *(float4*)(oA + base) = aA;
        *(float4*)(oB + base) = aB;
        *(float4*)(oC + base) = aC;
        float4* ap = (float4*)(acc + base);
        float4 t = *ap;
        t.x += aC.x; t.y += aC.y; t.z += aC.z; t.w += aC.w;
        *ap = t;
    }
}

__device__ __forceinline__ void dev_finalize(const float* __restrict__ acc,
                                             const float* __restrict__ A,
                                             const float* __restrict__ B,
                                             float* __restrict__ out, int n, int bid) {
    int row = bid * 8 + ((int)threadIdx.x >> 5);
    if (row >= n) return;
    int lane = threadIdx.x & 31;
    size_t base = (size_t)row * 64 + lane * 2;
    float2 a = *(const float2*)(A + base);
    float2 b = *(const float2*)(B + base);
    float2 ac = *(const float2*)(acc + base);
    float sa = a.x * a.x + a.y * a.y;
    float sb = b.x * b.x + b.y * b.y;
    #pragma unroll
    for (int o = 16; o; o >>= 1) {
        sa += __shfl_xor_sync(0xFFFFFFFFu, sa, o);
        sb += __shfl_xor_sync(0xFFFFFFFFu, sb, o);
    }
    float ka = CAT_RATE / fmaxf(sqrtf(sa), 1e-12f);
    float kb = CAT_RATE / fmaxf(sqrtf(sb), 1e-12f);
    const float inv_layers = 1.0f / 3.0f;
    float2 o2 = make_float2(ac.x * inv_layers + ka * a.x + kb * b.x,
                            ac.y * inv_layers + ka * a.y + kb * b.y);
    *(float2*)(out + base) = o2;
}

// ======================= phase kernels =======================

// P1: gemm-img || gemm-txt || hist || norm_stats
__global__ __launch_bounds__(256) void phase1(const float* __restrict__ imgF,
                                              const float* __restrict__ Wi,
                                              const float* __restrict__ bi,
                                              const float* __restrict__ txtF,
                                              const float* __restrict__ Wt,
                                              const float* __restrict__ bt,
                                              const int* __restrict__ eu,
                                              const int* __restrict__ ei,
                                              const float* __restrict__ ue,
                                              const float* __restrict__ ie) {
    __shared__ float Ws[64 * WS_STRIDE];
    int b = blockIdx.x;
    if (b < GB)               dev_gemm_tf32(imgF, Wi, bi, g_imgfeat, N_ITEMS, 1024, b, Ws);
    else if (b < 2 * GB)      dev_gemm_tf32(txtF, Wt, bt, g_txtfeat, N_ITEMS, 384, b - GB, Ws);
    else if (b < 2 * GB + HB) dev_hist(eu, ei, b - 2 * GB, HB);
    else                      dev_norm_stats(ue, ie, b - 2 * GB - HB, NSB);
}

// P2: block_sums u || block_sums i || norm_finalize
__global__ __launch_bounds__(256) void phase2() {
    int b = blockIdx.x;
    if (b < NBU)            dev_block_sums(g_ucnt, N_USERS, g_upart, b);
    else if (b < NBU + NBI) dev_block_sums(g_icnt, N_ITEMS, g_ipart, b - NBU);
    else                    dev_norm_finalize();
}

// P3: small scans + tails
__global__ __launch_bounds__(128) void phase3() {
    if (blockIdx.x == 0) {
        dev_scan_small(g_upart, NBU);
        if (threadIdx.x == 0) { g_urp[N_USERS] = NE; g_irp[N_ITEMS] = NE; }
    } else {
        dev_scan_small(g_ipart, NBI);
    }
}

// P4: scan_chunks u/i only (small; apply_norm moved to P5)
__global__ __launch_bounds__(256) void phase4() {
    int b = blockIdx.x;
    if (b < NBU) dev_scan_chunks(g_ucnt, N_USERS, g_upart, g_urp, g_ucur, b);
    else         dev_scan_chunks(g_icnt, N_ITEMS, g_ipart, g_irp, g_icur, b - NBU);
}

// P5: scatter || apply_norm
__global__ __launch_bounds__(256) void phase5(const int* __restrict__ eu,
                                              const int* __restrict__ ei,
                                              const float* __restrict__ vui,
                                              const float* __restrict__ viu,
                                              const float* __restrict__ ue,
                                              const float* __restrict__ ie) {
    int b = blockIdx.x;
    if (b < SCB) dev_scatter(eu, ei, vui, viu, b, SCB);
    else         dev_apply_norm(ue, ie, b - SCB, APB);
}

// P6: triple-U: o_imgU, o_txtU, ug(layer1) + uacc
__global__ __launch_bounds__(256) void phase6(float* __restrict__ o_imgU,
                                              float* __restrict__ o_txtU) {
    dev_spmm3(g_urp, g_ucol, g_uval, g_imgfeat, g_txtfeat, g_ig,
              o_imgU, o_txtU, g_ug, g_uacc, N_USERS, blockIdx.x);
}

// P7: triple-I: o_imgI, o_txtI, ig(layer1) + iacc
__global__ __launch_bounds__(256) void phase7(const float* __restrict__ o_imgU,
                                              const float* __restrict__ o_txtU,
                                              float* __restrict__ o_imgI,
                                              float* __restrict__ o_txtI) {
    dev_spmm3(g_irp, g_icol, g_ival, o_imgU, o_txtU, g_ug,
              o_imgI, o_txtI, g_ig, g_iacc, N_ITEMS, blockIdx.x);
}

// P8: GNN layer-2 user spmm
__global__ __launch_bounds__(256) void phase8() {
    dev_spmm(g_urp, g_ucol, g_uval, g_ig, g_ug, g_uacc, N_USERS, blockIdx.x);
}

// P9: GNN layer-2 item spmm || finalize users
__global__ __launch_bounds__(256) void phase9(const float* __restrict__ o_imgU,
                                              const float* __restrict__ o_txtU,
                                              float* __restrict__ o_u) {
    int b = blockIdx.x;
    if (b < SBI) dev_spmm(g_irp, g_icol, g_ival, g_ug, g_ig, g_iacc, N_ITEMS, b);
    else         dev_finalize(g_uacc, o_imgU, o_txtU, o_u, N_USERS, b - SBI);
}

// P10: finalize items
__global__ __launch_bounds__(256) void phase10(const float* __restrict__ o_imgI,
                                               const float* __restrict__ o_txtI,
                                               float* __restrict__ o_i) {
    dev_finalize(g_iacc, o_imgI, o_txtI, o_i, N_ITEMS, blockIdx.x);
}

// ======================= launch =======================
extern "C" void kernel_launch(void* const* d_in, const int* in_sizes, int n_in,
                              void* d_out, int out_size) {
    const float* image_feats = (const float*)d_in[0];
    const float* text_feats  = (const float*)d_in[1];
    const float* user_emb    = (const float*)d_in[2];
    const float* item_emb    = (const float*)d_in[3];
    const float* W_img       = (const float*)d_in[4];
    const float* b_img       = (const float*)d_in[5];
    const float* W_txt       = (const float*)d_in[6];
    const float* b_txt       = (const float*)d_in[7];
    const float* val_ui      = (const float*)d_in[8];
    const float* val_iu      = (const float*)d_in[9];
    const int*   edge_u      = (const int*)d_in[10];
    const int*   edge_i      = (const int*)d_in[11];

    float* out = (float*)d_out;
    float* o_u    = out;                      // 100000*64
    float* o_i    = out + 6400000;            // 50000*64
    float* o_imgI = out + 9600000;            // 50000*64
    float* o_txtI = out + 12800000;           // 50000*64
    float* o_imgU = out + 16000000;           // 100000*64
    float* o_txtU = out + 22400000;           // 100000*64

    void *p;
    int *ucnt, *icnt; float *stats;
    cudaGetSymbolAddress(&p, g_ucnt);  ucnt  = (int*)p;
    cudaGetSymbolAddress(&p, g_icnt);  icnt  = (int*)p;
    cudaGetSymbolAddress(&p, g_stats); stats = (float*)p;

    cudaMemsetAsync(ucnt, 0, N_USERS * sizeof(int));
    cudaMemsetAsync(icnt, 0, N_ITEMS * sizeof(int));
    cudaMemsetAsync(stats, 0, 66 * sizeof(float));

    phase1<<<2 * GB + HB + NSB, 256>>>(image_feats, W_img, b_img,
                                       text_feats,  W_txt, b_txt,
                                       edge_u, edge_i, user_emb, item_emb);
    phase2<<<NBU + NBI + 1, 256>>>();
    phase3<<<2, 128>>>();
    phase4<<<NBU + NBI, 256>>>();
    phase5<<<SCB + APB, 256>>>(edge_u, edge_i, val_ui, val_iu, user_emb, item_emb);
    phase6<<<SBU, 256>>>(o_imgU, o_txtU);
    phase7<<<SBI, 256>>>(o_imgU, o_txtU, o_imgI, o_txtI);
    phase8<<<SBU, 256>>>();
    phase9<<<SBI + SBU, 256>>>(o_imgU, o_txtU, o_u);
    phase10<<<SBI, 256>>>(o_imgI, o_txtI, o_i);
}

// round 10
// speedup vs baseline: 1.3366x; 1.3366x over previous
#include <cuda_runtime.h>
#include <math.h>
#include <stdint.h>

#define N_USERS 100000
#define N_ITEMS 50000
#define DD      64
#define NE      2000000
#define CAT_RATE 0.55f

#define NBU 98          // ceil(100000/1024)
#define NBI 49          // ceil(50000/1024)
#define GB  391         // ceil(50000/128) gemm blocks per matrix
#define SBU 12500       // 100000 rows / 8 warps
#define SBI 6250        // 50000 rows / 8 warps
#define APB 1024        // apply_norm grid-stride blocks
#define HB  2048        // hist blocks
#define NSB 1024        // norm_stats blocks

// ------------------------- static device scratch (no allocs) -------------------------
__device__ float g_imgfeat[(size_t)N_ITEMS * DD];
__device__ float g_txtfeat[(size_t)N_ITEMS * DD];
__device__ float g_ug[(size_t)N_USERS * DD];
__device__ float g_uacc[(size_t)N_USERS * DD];
__device__ float g_ig[(size_t)N_ITEMS * DD];
__device__ float g_iacc[(size_t)N_ITEMS * DD];

__device__ int   g_ucnt[N_USERS];
__device__ int   g_icnt[N_ITEMS];
__device__ int   g_urp[N_USERS + 1];
__device__ int   g_irp[N_ITEMS + 1];
__device__ int   g_ucur[N_USERS];
__device__ int   g_icur[N_ITEMS];
__device__ int   g_ucol[NE];
__device__ float g_uval[NE];
__device__ int   g_icol[NE];
__device__ float g_ival[NE];
__device__ int   g_upart[128];
__device__ int   g_ipart[128];
__device__ float g_stats[66];   // [0..63] col means, [64] inv rownorm

// ======================= device role functions =======================

__device__ __forceinline__ void dev_hist(const int* __restrict__ eu,
                                         const int* __restrict__ ei,
                                         int bid, int nb) {
    int i = bid * 256 + threadIdx.x;
    int stride = nb * 256;
    for (; i < NE; i += stride) {
        atomicAdd(&g_ucnt[eu[i]], 1);
        atomicAdd(&g_icnt[ei[i]], 1);
    }
}

__device__ void dev_norm_stats(const float* __restrict__ ue,
                               const float* __restrict__ ie,
                               int bid, int nb) {
    int t = threadIdx.x;           // 256
    int c = t & 63;
    int rsub = t >> 6;             // 0..3
    float s = 0.f, q = 0.f;
    for (int r = bid * 4 + rsub; r < N_USERS + N_ITEMS; r += nb * 4) {
        const float* src = (r < N_USERS) ? (ue + (size_t)r * 64)
                                         : (ie + (size_t)(r - N_USERS) * 64);
        float v = src[c];
        s += v; q += v * v;
    }
    __shared__ float scol[256], sq[256];
    scol[t] = s; sq[t] = q;
    __syncthreads();
    for (int st = 128; st > 0; st >>= 1) { if (t < st) sq[t] += sq[t + st]; __syncthreads(); }
    if (t < 64) {
        float cs = scol[t] + scol[t + 64] + scol[t + 128] + scol[t + 192];
        atomicAdd(&g_stats[t], cs);
    }
    if (t == 0) atomicAdd(&g_stats[64], sq[0]);
}

// ---------------- tf32 tensor-core GEMM: out[M,64] = A[M,K] @ W[K,64] + b -----------
__device__ __forceinline__ uint32_t f2tf32(float f) {
    uint32_t u;
    asm("cvt.rna.tf32.f32 %0, %1;" : "=r"(u) : "f"(f));
    return u;
}

#define WS_STRIDE 76    // floats per row (padded, float4-aligned, conflict-spread)

__device__ void dev_gemm_tf32(const float* __restrict__ A,
                              const float* __restrict__ W,
                              const float* __restrict__ bias,
                              float* __restrict__ out, int M, int K, int bid,
                              float* Ws /* [64*WS_STRIDE] smem */) {
    int tid  = threadIdx.x;
    int warp = tid >> 5, lane = tid & 31;
    int gid  = lane >> 2, tid4 = lane & 3;
    int rA = bid * 128 + warp * 16 + gid;
    int rB = rA + 8;
    bool okA = rA < M, okB = rB < M;
    const float* ArA = A + (size_t)rA * K;
    const float* ArB = A + (size_t)rB * K;

    float c[8][4];
    #pragma unroll
    for (int t = 0; t < 8; ++t) { c[t][0]=0.f; c[t][1]=0.f; c[t][2]=0.f; c[t][3]=0.f; }

    for (int k0 = 0; k0 < K; k0 += 64) {
        #pragma unroll
        for (int i = 0; i < 4; ++i) {
            int li = tid + i * 256;
            int r = li >> 4;
            int cb = (li & 15) * 4;
            float4 w = *(const float4*)(W + (size_t)(k0 + r) * 64 + cb);
            float* wr = Ws + r * WS_STRIDE;
            wr[((cb + 0) & 7) * 8 + ((cb + 0) >> 3)] = __uint_as_float(f2tf32(w.x));
            wr[((cb + 1) & 7) * 8 + ((cb + 1) >> 3)] = __uint_as_float(f2tf32(w.y));
            wr[((cb + 2) & 7) * 8 + ((cb + 2) >> 3)] = __uint_as_float(f2tf32(w.z));
            wr[((cb + 3) & 7) * 8 + ((cb + 3) >> 3)] = __uint_as_float(f2tf32(w.w));
        }
        __syncthreads();
        #pragma unroll
        for (int ks = 0; ks < 8; ++ks) {
            int kk = k0 + ks * 8;
            float a0 = 0.f, a1 = 0.f, a2 = 0.f, a3 = 0.f;
            if (okA) { a0 = ArA[kk + tid4]; a2 = ArA[kk + tid4 + 4]; }
            if (okB) { a1 = ArB[kk + tid4]; a3 = ArB[kk + tid4 + 4]; }
            uint32_t ua0 = f2tf32(a0), ua1 = f2tf32(a1);
            uint32_t ua2 = f2tf32(a2), ua3 = f2tf32(a3);
            const float* w0 = Ws + (ks * 8 + tid4) * WS_STRIDE + gid * 8;
            const float* w1 = Ws + (ks * 8 + tid4 + 4) * WS_STRIDE + gid * 8;
            float b0arr[8], b1arr[8];
            *(float4*)&b0arr[0] = *(const float4*)(w0);
            *(float4*)&b0arr[4] = *(const float4*)(w0 + 4);
            *(float4*)&b1arr[0] = *(const float4*)(w1);
            *(float4*)&b1arr[4] = *(const float4*)(w1 + 4);
            #pragma unroll
            for (int t = 0; t < 8; ++t) {
                uint32_t ub0 = __float_as_uint(b0arr[t]);
                uint32_t ub1 = __float_as_uint(b1arr[t]);
                asm volatile(
                    "mma.sync.aligned.m16n8k8.row.col.f32.tf32.tf32.f32 "
                    "{%0,%1,%2,%3}, {%4,%5,%6,%7}, {%8,%9}, {%0,%1,%2,%3};"
                    : "+f"(c[t][0]), "+f"(c[t][1]), "+f"(c[t][2]), "+f"(c[t][3])
                    : "r"(ua0), "r"(ua1), "r"(ua2), "r"(ua3), "r"(ub0), "r"(ub1));
            }
        }
        __syncthreads();
    }
    #pragma unroll
    for (int t = 0; t < 8; ++t) {
        int n = t * 8 + 2 * tid4;
        float bx = bias[n], by = bias[n + 1];
        if (okA) *(float2*)(out + (size_t)rA * 64 + n) = make_float2(c[t][0] + bx, c[t][1] + by);
        if (okB) *(float2*)(out + (size_t)rB * 64 + n) = make_float2(c[t][2] + bx, c[t][3] + by);
    }
}

// ---------------- CSR scan helpers ----------------
__device__ void dev_block_sums(const int* __restrict__ cnt, int n,
                               int* __restrict__ part, int bid) {
    __shared__ int sm[256];
    int t = threadIdx.x;
    int base = bid * 1024;
    int s = 0;
    #pragma unroll
    for (int r = 0; r < 4; ++r) {
        int idx = base + t * 4 + r;
        if (idx < n) s += cnt[idx];
    }
    sm[t] = s; __syncthreads();
    for (int st = 128; st > 0; st >>= 1) { if (t < st) sm[t] += sm[t + st]; __syncthreads(); }
    if (t == 0) part[bid] = sm[0];
}

__device__ void dev_norm_finalize() {
    __shared__ float smf[64];
    int t = threadIdx.x;
    if (t < 64) {
        float n = (float)(N_USERS + N_ITEMS);
        float mean = g_stats[t] / n;
        smf[t] = mean * mean;
    }
    __syncthreads();
    if (t == 0) {
        float ssum = 0.f;
        #pragma unroll
        for (int i = 0; i < 64; ++i) ssum += smf[i];
        float n = (float)(N_USERS + N_ITEMS);
        float Q = g_stats[64];
        smf[0] = rsqrtf(Q / n - ssum + 1e-6f);
    }
    __syncthreads();
    if (t < 64) g_stats[t] = g_stats[t] / (float)(N_USERS + N_ITEMS);
    __syncthreads();
    if (t == 0) g_stats[64] = smf[0];
}

__device__ void dev_scan_small(int* __restrict__ part, int n) {
    __shared__ int sm[128];
    int t = threadIdx.x;   // 128 threads
    int v = (t < n) ? part[t] : 0;
    sm[t] = v; __syncthreads();
    for (int off = 1; off < 128; off <<= 1) {
        int x = (t >= off) ? sm[t - off] : 0;
        __syncthreads();
        sm[t] += x;
        __syncthreads();
    }
    part[t] = sm[t] - v;   // exclusive
}

__device__ void dev_scan_chunks(const int* __restrict__ cnt, int n,
                                const int* __restrict__ part,
                                int* __restrict__ rp, int* __restrict__ cur, int bid) {
    __shared__ int sm[256];
    int t = threadIdx.x;
    int base = bid * 1024;
    int v[4]; int local = 0;
    #pragma unroll
    for (int r = 0; r < 4; ++r) {
        int idx = base + t * 4 + r;
        v[r] = (idx < n) ? cnt[idx] : 0;
        local += v[r];
    }
    sm[t] = local; __syncthreads();
    for (int off = 1; off < 256; off <<= 1) {
        int x = (t >= off) ? sm[t - off] : 0;
        __syncthreads();
        sm[t] += x;
        __syncthreads();
    }
    int excl = sm[t] - local + part[bid];
    #pragma unroll
    for (int r = 0; r < 4; ++r) {
        int idx = base + t * 4 + r;
        if (idx < n) { rp[idx] = excl; cur[idx] = excl; }
        excl += v[r];
    }
}

__device__ void dev_apply_norm(const float* __restrict__ ue,
                               const float* __restrict__ ie, int bid, int nb) {
    float inv = g_stats[64];
    int idx = bid * 256 + threadIdx.x;
    int stride = nb * 256;
    const int NU = N_USERS * 64;
    const int NT = (N_USERS + N_ITEMS) * 64;
    for (; idx < NT; idx += stride) {
        int c = idx & 63;
        if (idx < NU) {
            float v = (ue[idx] - g_stats[c]) * inv;
            g_ug[idx] = v; g_uacc[idx] = v;
        } else {
            int j = idx - NU;
            float v = (ie[j] - g_stats[c]) * inv;
            g_ig[j] = v; g_iacc[j] = v;
        }
    }
}

__device__ void dev_scatter(const int* __restrict__ eu, const int* __restrict__ ei,
                            const float* __restrict__ vui, const float* __restrict__ viu,
                            int bid, int nb) {
    int i = bid * 256 + threadIdx.x;
    int stride = nb * 256;
    for (; i < NE; i += stride) {
        int u = eu[i], it = ei[i];
        int p = atomicAdd(&g_ucur[u], 1);
        g_ucol[p] = it; g_uval[p] = vui[i];
        int q = atomicAdd(&g_icur[it], 1);
        g_icol[q] = u; g_ival[q] = viu[i];
    }
}

// ---------------- SpMM variants (warp/row, lane = 2 cols, 2-edge unroll) ----------------
__device__ __forceinline__ void dev_spmm(const int* __restrict__ rp,
                                         const int* __restrict__ cols,
                                         const float* __restrict__ vals,
                                         const float* __restrict__ src,
                                         float* __restrict__ out,
                                         float* __restrict__ acc,
                                         int n_rows, int bid) {
    int row = bid * 8 + ((int)threadIdx.x >> 5);
    if (row >= n_rows) return;
    int lane = threadIdx.x & 31;
    int s = rp[row], e = rp[row + 1];
    float ax = 0.f, ay = 0.f;
    int j = s;
    for (; j + 2 <= e; j += 2) {
        float v0 = __ldg(&vals[j]);     int c0 = __ldg(&cols[j]);
        float v1 = __ldg(&vals[j + 1]); int c1 = __ldg(&cols[j + 1]);
        float2 s0 = *(const float2*)(src + (size_t)c0 * 64 + lane * 2);
        float2 s1 = *(const float2*)(src + (size_t)c1 * 64 + lane * 2);
        ax = fmaf(v0, s0.x, ax); ay = fmaf(v0, s0.y, ay);
        ax = fmaf(v1, s1.x, ax); ay = fmaf(v1, s1.y, ay);
    }
    if (j < e) {
        float v = __ldg(&vals[j]); int c = __ldg(&cols[j]);
        float2 sv = *(const float2*)(src + (size_t)c * 64 + lane * 2);
        ax = fmaf(v, sv.x, ax); ay = fmaf(v, sv.y, ay);
    }
    size_t base = (size_t)row * 64 + lane * 2;
    *(float2*)(out + base) = make_float2(ax, ay);
    if (acc) {
        float2* ap = (float2*)(acc + base);
        float2 t = *ap;
        t.x += ax; t.y += ay;
        *ap = t;
    }
}

// triple-source: same CSR, three feature tables, acc on third output; 2-edge unroll
__device__ __forceinline__ void dev_spmm3(const int* __restrict__ rp,
                                          const int* __restrict__ cols,
                                          const float* __restrict__ vals,
                                          const float* __restrict__ sA,
                                          const float* __restrict__ sB,
                                          const float* __restrict__ sC,
                                          float* __restrict__ oA,
                                          float* __restrict__ oB,
                                          float* __restrict__ oC,
                                          float* __restrict__ acc,
                                          int n_rows, int bid) {
    int row = bid * 8 + ((int)threadIdx.x >> 5);
    if (row >= n_rows) return;
    int lane = threadIdx.x & 31;
    int s = rp[row], e = rp[row + 1];
    float aAx=0.f, aAy=0.f, aBx=0.f, aBy=0.f, aCx=0.f, aCy=0.f;
    int j = s;
    for (; j + 2 <= e; j += 2) {
        float v0 = __ldg(&vals[j]);     int c0 = __ldg(&cols[j]);
        float v1 = __ldg(&vals[j + 1]); int c1 = __ldg(&cols[j + 1]);
        size_t o0 = (size_t)c0 * 64 + lane * 2;
        size_t o1 = (size_t)c1 * 64 + lane * 2;
        float2 a0 = *(const float2*)(sA + o0);
        float2 b0 = *(const float2*)(sB + o0);
        float2 d0 = *(const float2*)(sC + o0);
        float2 a1 = *(const float2*)(sA + o1);
        float2 b1 = *(const float2*)(sB + o1);
        float2 d1 = *(const float2*)(sC + o1);
        aAx = fmaf(v0, a0.x, aAx); aAy = fmaf(v0, a0.y, aAy);
        aBx = fmaf(v0, b0.x, aBx); aBy = fmaf(v0, b0.y, aBy);
        aCx = fmaf(v0, d0.x, aCx); aCy = fmaf(v0, d0.y, aCy);
        aAx = fmaf(v1, a1.x, aAx); aAy = fmaf(v1, a1.y, aAy);
        aBx = fmaf(v1, b1.x, aBx); aBy = fmaf(v1, b1.y, aBy);
        aCx = fmaf(v1, d1.x, aCx); aCy = fmaf(v1, d1.y, aCy);
    }
    if (j < e) {
        float v = __ldg(&vals[j]); int c = __ldg(&cols[j]);
        size_t o = (size_t)c * 64 + lane * 2;
        float2 a = *(const float2*)(sA + o);
        float2 b = *(const float2*)(sB + o);
        float2 d = *(const float2*)(sC + o);
        aAx = fmaf(v, a.x, aAx); aAy = fmaf(v, a.y, aAy);
        aBx = fmaf(v, b.x, aBx); aBy = fmaf(v, b.y, aBy);
        aCx = fmaf(v, d.x, aCx); aCy = fmaf(v, d.y, aCy);
    }
    size_t base = (size_t)row * 64 + lane * 2;
    *(float2*)(oA + base) = make_float2(aAx, aAy);
    *(float2*)(oB + base) = make_float2(aBx, aBy);
    *(float2*)(oC + base) = make_float2(aCx, aCy);
    float2* ap = (float2*)(acc + base);
    float2 t = *ap;
    t.x += aCx; t.y += aCy;
    *ap = t;
}

__device__ __forceinline__ void dev_finalize(const float* __restrict__ acc,
                                             const float* __restrict__ A,
                                             const float* __restrict__ B,
                                             float* __restrict__ out, int n, int bid) {
    int row = bid * 8 + ((int)threadIdx.x >> 5);
    if (row >= n) return;
    int lane = threadIdx.x & 31;
    size_t base = (size_t)row * 64 + lane * 2;
    float2 a = *(const float2*)(A + base);
    float2 b = *(const float2*)(B + base);
    float2 ac = *(const float2*)(acc + base);
    float sa = a.x * a.x + a.y * a.y;
    float sb = b.x * b.x + b.y * b.y;
    #pragma unroll
    for (int o = 16; o; o >>= 1) {
        sa += __shfl_xor_sync(0xFFFFFFFFu, sa, o);
        sb += __shfl_xor_sync(0xFFFFFFFFu, sb, o);
    }
    float ka = CAT_RATE / fmaxf(sqrtf(sa), 1e-12f);
    float kb = CAT_RATE / fmaxf(sqrtf(sb), 1e-12f);
    const float inv_layers = 1.0f / 3.0f;
    float2 o2 = make_float2(ac.x * inv_layers + ka * a.x + kb * b.x,
                            ac.y * inv_layers + ka * a.y + kb * b.y);
    *(float2*)(out + base) = o2;
}

// ======================= phase kernels =======================

// P1: gemm-img || gemm-txt || hist || norm_stats
__global__ __launch_bounds__(256) void phase1(const float* __restrict__ imgF,
                                              const float* __restrict__ Wi,
                                              const float* __restrict__ bi,
                                              const float* __restrict__ txtF,
                                              const float* __restrict__ Wt,
                                              const float* __restrict__ bt,
                                              const int* __restrict__ eu,
                                              const int* __restrict__ ei,
                                              const float* __restrict__ ue,
                                              const float* __restrict__ ie) {
    __shared__ float Ws[64 * WS_STRIDE];
    int b = blockIdx.x;
    if (b < GB)               dev_gemm_tf32(imgF, Wi, bi, g_imgfeat, N_ITEMS, 1024, b, Ws);
    else if (b < 2 * GB)      dev_gemm_tf32(txtF, Wt, bt, g_txtfeat, N_ITEMS, 384, b - GB, Ws);
    else if (b < 2 * GB + HB) dev_hist(eu, ei, b - 2 * GB, HB);
    else                      dev_norm_stats(ue, ie, b - 2 * GB - HB, NSB);
}

// P2: block_sums u || block_sums i || norm_finalize
__global__ __launch_bounds__(256) void phase2() {
    int b = blockIdx.x;
    if (b < NBU)            dev_block_sums(g_ucnt, N_USERS, g_upart, b);
    else if (b < NBU + NBI) dev_block_sums(g_icnt, N_ITEMS, g_ipart, b - NBU);
    else                    dev_norm_finalize();
}

// P3: small scans + tails
__global__ __launch_bounds__(128) void phase3() {
    if (blockIdx.x == 0) {
        dev_scan_small(g_upart, NBU);
        if (threadIdx.x == 0) { g_urp[N_USERS] = NE; g_irp[N_ITEMS] = NE; }
    } else {
        dev_scan_small(g_ipart, NBI);
    }
}

// P4: scan_chunks u/i || apply_norm
__global__ __launch_bounds__(256) void phase4(const float* __restrict__ ue,
                                              const float* __restrict__ ie) {
    int b = blockIdx.x;
    if (b < NBU)            dev_scan_chunks(g_ucnt, N_USERS, g_upart, g_urp, g_ucur, b);
    else if (b < NBU + NBI) dev_scan_chunks(g_icnt, N_ITEMS, g_ipart, g_irp, g_icur, b - NBU);
    else                    dev_apply_norm(ue, ie, b - NBU - NBI, APB);
}

// P5: scatter
__global__ __launch_bounds__(256) void phase5(const int* __restrict__ eu,
                                              const int* __restrict__ ei,
                                              const float* __restrict__ vui,
                                              const float* __restrict__ viu) {
    dev_scatter(eu, ei, vui, viu, blockIdx.x, gridDim.x);
}

// P6: triple-U: o_imgU, o_txtU, ug(layer1) + uacc
__global__ __launch_bounds__(256) void phase6(float* __restrict__ o_imgU,
                                              float* __restrict__ o_txtU) {
    dev_spmm3(g_urp, g_ucol, g_uval, g_imgfeat, g_txtfeat, g_ig,
              o_imgU, o_txtU, g_ug, g_uacc, N_USERS, blockIdx.x);
}

// P7: triple-I: o_imgI, o_txtI, ig(layer1) + iacc
__global__ __launch_bounds__(256) void phase7(const float* __restrict__ o_imgU,
                                              const float* __restrict__ o_txtU,
                                              float* __restrict__ o_imgI,
                                              float* __restrict__ o_txtI) {
    dev_spmm3(g_irp, g_icol, g_ival, o_imgU, o_txtU, g_ug,
              o_imgI, o_txtI, g_ig, g_iacc, N_ITEMS, blockIdx.x);
}

// P8: GNN layer-2 user spmm
__global__ __launch_bounds__(256) void phase8() {
    dev_spmm(g_urp, g_ucol, g_uval, g_ig, g_ug, g_uacc, N_USERS, blockIdx.x);
}

// P9: GNN layer-2 item spmm || finalize users
__global__ __launch_bounds__(256) void phase9(const float* __restrict__ o_imgU,
                                              const float* __restrict__ o_txtU,
                                              float* __restrict__ o_u) {
    int b = blockIdx.x;
    if (b < SBI) dev_spmm(g_irp, g_icol, g_ival, g_ug, g_ig, g_iacc, N_ITEMS, b);
    else         dev_finalize(g_uacc, o_imgU, o_txtU, o_u, N_USERS, b - SBI);
}

// P10: finalize items
__global__ __launch_bounds__(256) void phase10(const float* __restrict__ o_imgI,
                                               const float* __restrict__ o_txtI,
                                               float* __restrict__ o_i) {
    dev_finalize(g_iacc, o_imgI, o_txtI, o_i, N_ITEMS, blockIdx.x);
}

// ======================= launch =======================
extern "C" void kernel_launch(void* const* d_in, const int* in_sizes, int n_in,
                              void* d_out, int out_size) {
    const float* image_feats = (const float*)d_in[0];
    const float* text_feats  = (const float*)d_in[1];
    const float* user_emb    = (const float*)d_in[2];
    const float* item_emb    = (const float*)d_in[3];
    const float* W_img       = (const float*)d_in[4];
    const float* b_img       = (const float*)d_in[5];
    const float* W_txt       = (const float*)d_in[6];
    const float* b_txt       = (const float*)d_in[7];
    const float* val_ui      = (const float*)d_in[8];
    const float* val_iu      = (const float*)d_in[9];
    const int*   edge_u      = (const int*)d_in[10];
    const int*   edge_i      = (const int*)d_in[11];

    float* out = (float*)d_out;
    float* o_u    = out;                      // 100000*64
    float* o_i    = out + 6400000;            // 50000*64
    float* o_imgI = out + 9600000;            // 50000*64
    float* o_txtI = out + 12800000;           // 50000*64
    float* o_imgU = out + 16000000;           // 100000*64
    float* o_txtU = out + 22400000;           // 100000*64

    void *p;
    int *ucnt, *icnt; float *stats;
    cudaGetSymbolAddress(&p, g_ucnt);  ucnt  = (int*)p;
    cudaGetSymbolAddress(&p, g_icnt);  icnt  = (int*)p;
    cudaGetSymbolAddress(&p, g_stats); stats = (float*)p;

    cudaMemsetAsync(ucnt, 0, N_USERS * sizeof(int));
    cudaMemsetAsync(icnt, 0, N_ITEMS * sizeof(int));
    cudaMemsetAsync(stats, 0, 66 * sizeof(float));

    phase1<<<2 * GB + HB + NSB, 256>>>(image_feats, W_img, b_img,
                                       text_feats,  W_txt, b_txt,
                                       edge_u, edge_i, user_emb, item_emb);
    phase2<<<NBU + NBI + 1, 256>>>();
    phase3<<<2, 128>>>();
    phase4<<<NBU + NBI + APB, 256>>>(user_emb, item_emb);
    phase5<<<2048, 256>>>(edge_u, edge_i, val_ui, val_iu);
    phase6<<<SBU, 256>>>(o_imgU, o_txtU);
    phase7<<<SBI, 256>>>(o_imgU, o_txtU, o_imgI, o_txtI);
    phase8<<<SBU, 256>>>();
    phase9<<<SBI + SBU, 256>>>(o_imgU, o_txtU, o_u);
    phase10<<<SBI, 256>>>(o_imgI, o_txtI, o_i);
}

// round 13
// speedup vs baseline: 1.4515x; 1.0860x over previous
#include <cuda_runtime.h>
#include <cuda_fp16.h>
#include <math.h>
#include <stdint.h>

#define N_USERS 100000
#define N_ITEMS 50000
#define DD      64
#define NE      2000000
#define CAT_RATE 0.55f

#define NBU 98          // ceil(100000/1024)
#define NBI 49          // ceil(50000/1024)
#define GB  391         // ceil(50000/128) gemm blocks per matrix
#define SBU 12500       // 100000 rows / 8 warps
#define SBI 6250        // 50000 rows / 8 warps
#define APB 1024        // apply_norm grid-stride blocks
#define HB  2048        // hist blocks
#define NSB 1024        // norm_stats blocks

// ------------------------- static device scratch (no allocs) -------------------------
// half2 tables for SpMM gathers (32 half2 = 64 halfs per row)
__device__ __half2 g_imgfeat_h[(size_t)N_ITEMS * 32];
__device__ __half2 g_txtfeat_h[(size_t)N_ITEMS * 32];
__device__ __half2 g_ug_h[(size_t)N_USERS * 32];
__device__ __half2 g_ig_h[(size_t)N_ITEMS * 32];
__device__ __half2 g_imgU_h[(size_t)N_USERS * 32];
__device__ __half2 g_txtU_h[(size_t)N_USERS * 32];
// fp32 accumulators
__device__ float g_uacc[(size_t)N_USERS * DD];
__device__ float g_iacc[(size_t)N_ITEMS * DD];

__device__ int   g_ucnt[N_USERS];
__device__ int   g_icnt[N_ITEMS];
__device__ int   g_urp[N_USERS + 1];
__device__ int   g_irp[N_ITEMS + 1];
__device__ int   g_ucur[N_USERS];
__device__ int   g_icur[N_ITEMS];
__device__ int   g_ucol[NE];
__device__ float g_uval[NE];
__device__ int   g_icol[NE];
__device__ float g_ival[NE];
__device__ int   g_upart[128];
__device__ int   g_ipart[128];
__device__ float g_stats[66];   // [0..63] col means, [64] inv rownorm

// ======================= device role functions =======================

__device__ __forceinline__ void dev_hist(const int* __restrict__ eu,
                                         const int* __restrict__ ei,
                                         int bid, int nb) {
    int i = bid * 256 + threadIdx.x;
    int stride = nb * 256;
    for (; i < NE; i += stride) {
        atomicAdd(&g_ucnt[eu[i]], 1);
        atomicAdd(&g_icnt[ei[i]], 1);
    }
}

__device__ void dev_norm_stats(const float* __restrict__ ue,
                               const float* __restrict__ ie,
                               int bid, int nb) {
    int t = threadIdx.x;           // 256
    int c = t & 63;
    int rsub = t >> 6;             // 0..3
    float s = 0.f, q = 0.f;
    for (int r = bid * 4 + rsub; r < N_USERS + N_ITEMS; r += nb * 4) {
        const float* src = (r < N_USERS) ? (ue + (size_t)r * 64)
                                         : (ie + (size_t)(r - N_USERS) * 64);
        float v = src[c];
        s += v; q += v * v;
    }
    __shared__ float scol[256], sq[256];
    scol[t] = s; sq[t] = q;
    __syncthreads();
    for (int st = 128; st > 0; st >>= 1) { if (t < st) sq[t] += sq[t + st]; __syncthreads(); }
    if (t < 64) {
        float cs = scol[t] + scol[t + 64] + scol[t + 128] + scol[t + 192];
        atomicAdd(&g_stats[t], cs);
    }
    if (t == 0) atomicAdd(&g_stats[64], sq[0]);
}

// ---------------- tf32 tensor-core GEMM -> half2 output table -----------
__device__ __forceinline__ uint32_t f2tf32(float f) {
    uint32_t u;
    asm("cvt.rna.tf32.f32 %0, %1;" : "=r"(u) : "f"(f));
    return u;
}

#define WS_STRIDE 76    // floats per row (padded, float4-aligned, conflict-spread)

__device__ void dev_gemm_tf32(const float* __restrict__ A,
                              const float* __restrict__ W,
                              const float* __restrict__ bias,
                              __half2* __restrict__ out_h, int M, int K, int bid,
                              float* Ws /* [64*WS_STRIDE] smem */) {
    int tid  = threadIdx.x;
    int warp = tid >> 5, lane = tid & 31;
    int gid  = lane >> 2, tid4 = lane & 3;
    int rA = bid * 128 + warp * 16 + gid;
    int rB = rA + 8;
    bool okA = rA < M, okB = rB < M;
    const float* ArA = A + (size_t)rA * K;
    const float* ArB = A + (size_t)rB * K;

    float c[8][4];
    #pragma unroll
    for (int t = 0; t < 8; ++t) { c[t][0]=0.f; c[t][1]=0.f; c[t][2]=0.f; c[t][3]=0.f; }

    for (int k0 = 0; k0 < K; k0 += 64) {
        #pragma unroll
        for (int i = 0; i < 4; ++i) {
            int li = tid + i * 256;
            int r = li >> 4;
            int cb = (li & 15) * 4;
            float4 w = *(const float4*)(W + (size_t)(k0 + r) * 64 + cb);
            float* wr = Ws + r * WS_STRIDE;
            wr[((cb + 0) & 7) * 8 + ((cb + 0) >> 3)] = __uint_as_float(f2tf32(w.x));
            wr[((cb + 1) & 7) * 8 + ((cb + 1) >> 3)] = __uint_as_float(f2tf32(w.y));
            wr[((cb + 2) & 7) * 8 + ((cb + 2) >> 3)] = __uint_as_float(f2tf32(w.z));
            wr[((cb + 3) & 7) * 8 + ((cb + 3) >> 3)] = __uint_as_float(f2tf32(w.w));
        }
        __syncthreads();
        #pragma unroll
        for (int ks = 0; ks < 8; ++ks) {
            int kk = k0 + ks * 8;
            float a0 = 0.f, a1 = 0.f, a2 = 0.f, a3 = 0.f;
            if (okA) { a0 = ArA[kk + tid4]; a2 = ArA[kk + tid4 + 4]; }
            if (okB) { a1 = ArB[kk + tid4]; a3 = ArB[kk + tid4 + 4]; }
            uint32_t ua0 = f2tf32(a0), ua1 = f2tf32(a1);
            uint32_t ua2 = f2tf32(a2), ua3 = f2tf32(a3);
            const float* w0 = Ws + (ks * 8 + tid4) * WS_STRIDE + gid * 8;
            const float* w1 = Ws + (ks * 8 + tid4 + 4) * WS_STRIDE + gid * 8;
            float b0arr[8], b1arr[8];
            *(float4*)&b0arr[0] = *(const float4*)(w0);
            *(float4*)&b0arr[4] = *(const float4*)(w0 + 4);
            *(float4*)&b1arr[0] = *(const float4*)(w1);
            *(float4*)&b1arr[4] = *(const float4*)(w1 + 4);
            #pragma unroll
            for (int t = 0; t < 8; ++t) {
                uint32_t ub0 = __float_as_uint(b0arr[t]);
                uint32_t ub1 = __float_as_uint(b1arr[t]);
                asm volatile(
                    "mma.sync.aligned.m16n8k8.row.col.f32.tf32.tf32.f32 "
                    "{%0,%1,%2,%3}, {%4,%5,%6,%7}, {%8,%9}, {%0,%1,%2,%3};"
                    : "+f"(c[t][0]), "+f"(c[t][1]), "+f"(c[t][2]), "+f"(c[t][3])
                    : "r"(ua0), "r"(ua1), "r"(ua2), "r"(ua3), "r"(ub0), "r"(ub1));
            }
        }
        __syncthreads();
    }
    #pragma unroll
    for (int t = 0; t < 8; ++t) {
        int n = t * 8 + 2 * tid4;              // even
        float bx = bias[n], by = bias[n + 1];
        if (okA) out_h[(size_t)rA * 32 + (n >> 1)] = __floats2half2_rn(c[t][0] + bx, c[t][1] + by);
        if (okB) out_h[(size_t)rB * 32 + (n >> 1)] = __floats2half2_rn(c[t][2] + bx, c[t][3] + by);
    }
}

// ---------------- CSR scan helpers ----------------
__device__ void dev_block_sums(const int* __restrict__ cnt, int n,
                               int* __restrict__ part, int bid) {
    __shared__ int sm[256];
    int t = threadIdx.x;
    int base = bid * 1024;
    int s = 0;
    #pragma unroll
    for (int r = 0; r < 4; ++r) {
        int idx = base + t * 4 + r;
        if (idx < n) s += cnt[idx];
    }
    sm[t] = s; __syncthreads();
    for (int st = 128; st > 0; st >>= 1) { if (t < st) sm[t] += sm[t + st]; __syncthreads(); }
    if (t == 0) part[bid] = sm[0];
}

__device__ void dev_norm_finalize() {
    __shared__ float smf[64];
    int t = threadIdx.x;
    if (t < 64) {
        float n = (float)(N_USERS + N_ITEMS);
        float mean = g_stats[t] / n;
        smf[t] = mean * mean;
    }
    __syncthreads();
    if (t == 0) {
        float ssum = 0.f;
        #pragma unroll
        for (int i = 0; i < 64; ++i) ssum += smf[i];
        float n = (float)(N_USERS + N_ITEMS);
        float Q = g_stats[64];
        smf[0] = rsqrtf(Q / n - ssum + 1e-6f);
    }
    __syncthreads();
    if (t < 64) g_stats[t] = g_stats[t] / (float)(N_USERS + N_ITEMS);
    __syncthreads();
    if (t == 0) g_stats[64] = smf[0];
}

__device__ void dev_scan_small(int* __restrict__ part, int n) {
    __shared__ int sm[128];
    int t = threadIdx.x;
    int v = (t < n) ? part[t] : 0;
    sm[t] = v; __syncthreads();
    for (int off = 1; off < 128; off <<= 1) {
        int x = (t >= off) ? sm[t - off] : 0;
        __syncthreads();
        sm[t] += x;
        __syncthreads();
    }
    part[t] = sm[t] - v;   // exclusive
}

__device__ void dev_scan_chunks(const int* __restrict__ cnt, int n,
                                const int* __restrict__ part,
                                int* __restrict__ rp, int* __restrict__ cur, int bid) {
    __shared__ int sm[256];
    int t = threadIdx.x;
    int base = bid * 1024;
    int v[4]; int local = 0;
    #pragma unroll
    for (int r = 0; r < 4; ++r) {
        int idx = base + t * 4 + r;
        v[r] = (idx < n) ? cnt[idx] : 0;
        local += v[r];
    }
    sm[t] = local; __syncthreads();
    for (int off = 1; off < 256; off <<= 1) {
        int x = (t >= off) ? sm[t - off] : 0;
        __syncthreads();
        sm[t] += x;
        __syncthreads();
    }
    int excl = sm[t] - local + part[bid];
    #pragma unroll
    for (int r = 0; r < 4; ++r) {
        int idx = base + t * 4 + r;
        if (idx < n) { rp[idx] = excl; cur[idx] = excl; }
        excl += v[r];
    }
}

// normalize + write half tables and fp32 acc (pair-wise)
__device__ void dev_apply_norm(const float* __restrict__ ue,
                               const float* __restrict__ ie, int bid, int nb) {
    float inv = g_stats[64];
    int idx = bid * 256 + threadIdx.x;          // pair index
    int stride = nb * 256;
    const int NUp = N_USERS * 32;
    const int NTp = (N_USERS + N_ITEMS) * 32;
    for (; idx < NTp; idx += stride) {
        int p = idx & 31;                       // pair col
        float m0 = g_stats[2 * p], m1 = g_stats[2 * p + 1];
        if (idx < NUp) {
            float2 e = *(const float2*)(ue + (size_t)idx * 2);
            float v0 = (e.x - m0) * inv, v1 = (e.y - m1) * inv;
            g_ug_h[idx] = __floats2half2_rn(v0, v1);
            *(float2*)(g_uacc + (size_t)idx * 2) = make_float2(v0, v1);
        } else {
            int j = idx - NUp;
            float2 e = *(const float2*)(ie + (size_t)j * 2);
            float v0 = (e.x - m0) * inv, v1 = (e.y - m1) * inv;
            g_ig_h[j] = __floats2half2_rn(v0, v1);
            *(float2*)(g_iacc + (size_t)j * 2) = make_float2(v0, v1);
        }
    }
}

__device__ void dev_scatter(const int* __restrict__ eu, const int* __restrict__ ei,
                            const float* __restrict__ vui, const float* __restrict__ viu,
                            int bid, int nb) {
    int i = bid * 256 + threadIdx.x;
    int stride = nb * 256;
    for (; i < NE; i += stride) {
        int u = eu[i], it = ei[i];
        int p = atomicAdd(&g_ucur[u], 1);
        g_ucol[p] = it; g_uval[p] = vui[i];
        int q = atomicAdd(&g_icur[it], 1);
        g_icol[q] = u; g_ival[q] = viu[i];
    }
}

// ---------------- half-gather SpMM (warp/row, lane = 1 half2 = 2 cols, 2-edge unroll) ----
__device__ __forceinline__ void dev_spmm_h(const int* __restrict__ rp,
                                           const int* __restrict__ cols,
                                           const float* __restrict__ vals,
                                           const __half2* __restrict__ src,
                                           __half2* __restrict__ out_h,
                                           float* __restrict__ acc,
                                           int n_rows, int bid) {
    int row = bid * 8 + ((int)threadIdx.x >> 5);
    if (row >= n_rows) return;
    int lane = threadIdx.x & 31;
    int s = rp[row], e = rp[row + 1];
    float ax = 0.f, ay = 0.f;
    int j = s;
    for (; j + 2 <= e; j += 2) {
        float v0 = __ldg(&vals[j]);     int c0 = __ldg(&cols[j]);
        float v1 = __ldg(&vals[j + 1]); int c1 = __ldg(&cols[j + 1]);
        float2 s0 = __half22float2(src[(size_t)c0 * 32 + lane]);
        float2 s1 = __half22float2(src[(size_t)c1 * 32 + lane]);
        ax = fmaf(v0, s0.x, ax); ay = fmaf(v0, s0.y, ay);
        ax = fmaf(v1, s1.x, ax); ay = fmaf(v1, s1.y, ay);
    }
    if (j < e) {
        float v = __ldg(&vals[j]); int c = __ldg(&cols[j]);
        float2 sv = __half22float2(src[(size_t)c * 32 + lane]);
        ax = fmaf(v, sv.x, ax); ay = fmaf(v, sv.y, ay);
    }
    size_t base = (size_t)row * 32 + lane;
    if (out_h) out_h[base] = __floats2half2_rn(ax, ay);
    if (acc) {
        float2* ap = (float2*)(acc + base * 2);
        float2 t = *ap;
        t.x += ax; t.y += ay;
        *ap = t;
    }
}

// triple-source half gather; fp32 outputs for A/B (+ optional half copies), half C + fp32 acc
__device__ __forceinline__ void dev_spmm3_h(const int* __restrict__ rp,
                                            const int* __restrict__ cols,
                                            const float* __restrict__ vals,
                                            const __half2* __restrict__ sA,
                                            const __half2* __restrict__ sB,
                                            const __half2* __restrict__ sC,
                                            float* __restrict__ oA32,
                                            float* __restrict__ oB32,
                                            __half2* __restrict__ oAh,
                                            __half2* __restrict__ oBh,
                                            __half2* __restrict__ oCh,
                                            float* __restrict__ acc,
                                            int n_rows, int bid) {
    int row = bid * 8 + ((int)threadIdx.x >> 5);
    if (row >= n_rows) return;
    int lane = threadIdx.x & 31;
    int s = rp[row], e = rp[row + 1];
    float aAx=0.f, aAy=0.f, aBx=0.f, aBy=0.f, aCx=0.f, aCy=0.f;
    int j = s;
    for (; j + 2 <= e; j += 2) {
        float v0 = __ldg(&vals[j]);     int c0 = __ldg(&cols[j]);
        float v1 = __ldg(&vals[j + 1]); int c1 = __ldg(&cols[j + 1]);
        size_t o0 = (size_t)c0 * 32 + lane;
        size_t o1 = (size_t)c1 * 32 + lane;
        float2 a0 = __half22float2(sA[o0]);
        float2 b0 = __half22float2(sB[o0]);
        float2 d0 = __half22float2(sC[o0]);
        float2 a1 = __half22float2(sA[o1]);
        float2 b1 = __half22float2(sB[o1]);
        float2 d1 = __half22float2(sC[o1]);
        aAx = fmaf(v0, a0.x, aAx); aAy = fmaf(v0, a0.y, aAy);
        aBx = fmaf(v0, b0.x, aBx); aBy = fmaf(v0, b0.y, aBy);
        aCx = fmaf(v0, d0.x, aCx); aCy = fmaf(v0, d0.y, aCy);
        aAx = fmaf(v1, a1.x, aAx); aAy = fmaf(v1, a1.y, aAy);
        aBx = fmaf(v1, b1.x, aBx); aBy = fmaf(v1, b1.y, aBy);
        aCx = fmaf(v1, d1.x, aCx); aCy = fmaf(v1, d1.y, aCy);
    }
    if (j < e) {
        float v = __ldg(&vals[j]); int c = __ldg(&cols[j]);
        size_t o = (size_t)c * 32 + lane;
        float2 a = __half22float2(sA[o]);
        float2 b = __half22float2(sB[o]);
        float2 d = __half22float2(sC[o]);
        aAx = fmaf(v, a.x, aAx); aAy = fmaf(v, a.y, aAy);
        aBx = fmaf(v, b.x, aBx); aBy = fmaf(v, b.y, aBy);
        aCx = fmaf(v, d.x, aCx); aCy = fmaf(v, d.y, aCy);
    }
    size_t base = (size_t)row * 32 + lane;
    *(float2*)(oA32 + base * 2) = make_float2(aAx, aAy);
    *(float2*)(oB32 + base * 2) = make_float2(aBx, aBy);
    if (oAh) oAh[base] = __floats2half2_rn(aAx, aAy);
    if (oBh) oBh[base] = __floats2half2_rn(aBx, aBy);
    oCh[base] = __floats2half2_rn(aCx, aCy);
    float2* ap = (float2*)(acc + base * 2);
    float2 t = *ap;
    t.x += aCx; t.y += aCy;
    *ap = t;
}

__device__ __forceinline__ void dev_finalize(const float* __restrict__ acc,
                                             const float* __restrict__ A,
                                             const float* __restrict__ B,
                                             float* __restrict__ out, int n, int bid) {
    int row = bid * 8 + ((int)threadIdx.x >> 5);
    if (row >= n) return;
    int lane = threadIdx.x & 31;
    size_t base = (size_t)row * 64 + lane * 2;
    float2 a = *(const float2*)(A + base);
    float2 b = *(const float2*)(B + base);
    float2 ac = *(const float2*)(acc + base);
    float sa = a.x * a.x + a.y * a.y;
    float sb = b.x * b.x + b.y * b.y;
    #pragma unroll
    for (int o = 16; o; o >>= 1) {
        sa += __shfl_xor_sync(0xFFFFFFFFu, sa, o);
        sb += __shfl_xor_sync(0xFFFFFFFFu, sb, o);
    }
    float ka = CAT_RATE / fmaxf(sqrtf(sa), 1e-12f);
    float kb = CAT_RATE / fmaxf(sqrtf(sb), 1e-12f);
    const float inv_layers = 1.0f / 3.0f;
    float2 o2 = make_float2(ac.x * inv_layers + ka * a.x + kb * b.x,
                            ac.y * inv_layers + ka * a.y + kb * b.y);
    *(float2*)(out + base) = o2;
}

// ======================= phase kernels =======================

// P1: gemm-img || gemm-txt || hist || norm_stats
__global__ __launch_bounds__(256) void phase1(const float* __restrict__ imgF,
                                              const float* __restrict__ Wi,
                                              const float* __restrict__ bi,
                                              const float* __restrict__ txtF,
                                              const float* __restrict__ Wt,
                                              const float* __restrict__ bt,
                                              const int* __restrict__ eu,
                                              const int* __restrict__ ei,
                                              const float* __restrict__ ue,
                                              const float* __restrict__ ie) {
    __shared__ float Ws[64 * WS_STRIDE];
    int b = blockIdx.x;
    if (b < GB)               dev_gemm_tf32(imgF, Wi, bi, g_imgfeat_h, N_ITEMS, 1024, b, Ws);
    else if (b < 2 * GB)      dev_gemm_tf32(txtF, Wt, bt, g_txtfeat_h, N_ITEMS, 384, b - GB, Ws);
    else if (b < 2 * GB + HB) dev_hist(eu, ei, b - 2 * GB, HB);
    else                      dev_norm_stats(ue, ie, b - 2 * GB - HB, NSB);
}

// P2: block_sums u || block_sums i || norm_finalize
__global__ __launch_bounds__(256) void phase2() {
    int b = blockIdx.x;
    if (b < NBU)            dev_block_sums(g_ucnt, N_USERS, g_upart, b);
    else if (b < NBU + NBI) dev_block_sums(g_icnt, N_ITEMS, g_ipart, b - NBU);
    else                    dev_norm_finalize();
}

// P3: small scans + tails
__global__ __launch_bounds__(128) void phase3() {
    if (blockIdx.x == 0) {
        dev_scan_small(g_upart, NBU);
        if (threadIdx.x == 0) { g_urp[N_USERS] = NE; g_irp[N_ITEMS] = NE; }
    } else {
        dev_scan_small(g_ipart, NBI);
    }
}

// P4: scan_chunks u/i || apply_norm
__global__ __launch_bounds__(256) void phase4(const float* __restrict__ ue,
                                              const float* __restrict__ ie) {
    int b = blockIdx.x;
    if (b < NBU)            dev_scan_chunks(g_ucnt, N_USERS, g_upart, g_urp, g_ucur, b);
    else if (b < NBU + NBI) dev_scan_chunks(g_icnt, N_ITEMS, g_ipart, g_irp, g_icur, b - NBU);
    else                    dev_apply_norm(ue, ie, b - NBU - NBI, APB);
}

// P5: scatter
__global__ __launch_bounds__(256) void phase5(const int* __restrict__ eu,
                                              const int* __restrict__ ei,
                                              const float* __restrict__ vui,
                                              const float* __restrict__ viu) {
    dev_scatter(eu, ei, vui, viu, blockIdx.x, gridDim.x);
}

// P6: triple-U
__global__ __launch_bounds__(256) void phase6(float* __restrict__ o_imgU,
                                              float* __restrict__ o_txtU) {
    dev_spmm3_h(g_urp, g_ucol, g_uval, g_imgfeat_h, g_txtfeat_h, g_ig_h,
                o_imgU, o_txtU, g_imgU_h, g_txtU_h, g_ug_h, g_uacc,
                N_USERS, blockIdx.x);
}

// P7: triple-I
__global__ __launch_bounds__(256) void phase7(float* __restrict__ o_imgI,
                                              float* __restrict__ o_txtI) {
    dev_spmm3_h(g_irp, g_icol, g_ival, g_imgU_h, g_txtU_h, g_ug_h,
                o_imgI, o_txtI, (__half2*)0, (__half2*)0, g_ig_h, g_iacc,
                N_ITEMS, blockIdx.x);
}

// P8: GNN layer-2 user spmm
__global__ __launch_bounds__(256) void phase8() {
    dev_spmm_h(g_urp, g_ucol, g_uval, g_ig_h, g_ug_h, g_uacc, N_USERS, blockIdx.x);
}

// P9: GNN layer-2 item spmm (acc only) || finalize users
__global__ __launch_bounds__(256) void phase9(const float* __restrict__ o_imgU,
                                              const float* __restrict__ o_txtU,
                                              float* __restrict__ o_u) {
    int b = blockIdx.x;
    if (b < SBI) dev_spmm_h(g_irp, g_icol, g_ival, g_ug_h, (__half2*)0, g_iacc, N_ITEMS, b);
    else         dev_finalize(g_uacc, o_imgU, o_txtU, o_u, N_USERS, b - SBI);
}

// P10: finalize items
__global__ __launch_bounds__(256) void phase10(const float* __restrict__ o_imgI,
                                               const float* __restrict__ o_txtI,
                                               float* __restrict__ o_i) {
    dev_finalize(g_iacc, o_imgI, o_txtI, o_i, N_ITEMS, blockIdx.x);
}

// ======================= launch =======================
extern "C" void kernel_launch(void* const* d_in, const int* in_sizes, int n_in,
                              void* d_out, int out_size) {
    const float* image_feats = (const float*)d_in[0];
    const float* text_feats  = (const float*)d_in[1];
    const float* user_emb    = (const float*)d_in[2];
    const float* item_emb    = (const float*)d_in[3];
    const float* W_img       = (const float*)d_in[4];
    const float* b_img       = (const float*)d_in[5];
    const float* W_txt       = (const float*)d_in[6];
    const float* b_txt       = (const float*)d_in[7];
    const float* val_ui      = (const float*)d_in[8];
    const float* val_iu      = (const float*)d_in[9];
    const int*   edge_u      = (const int*)d_in[10];
    const int*   edge_i      = (const int*)d_in[11];

    float* out = (float*)d_out;
    float* o_u    = out;                      // 100000*64
    float* o_i    = out + 6400000;            // 50000*64
    float* o_imgI = out + 9600000;            // 50000*64
    float* o_txtI = out + 12800000;           // 50000*64
    float* o_imgU = out + 16000000;           // 100000*64
    float* o_txtU = out + 22400000;           // 100000*64

    void *p;
    int *ucnt, *icnt; float *stats;
    cudaGetSymbolAddress(&p, g_ucnt);  ucnt  = (int*)p;
    cudaGetSymbolAddress(&p, g_icnt);  icnt  = (int*)p;
    cudaGetSymbolAddress(&p, g_stats); stats = (float*)p;

    cudaMemsetAsync(ucnt, 0, N_USERS * sizeof(int));
    cudaMemsetAsync(icnt, 0, N_ITEMS * sizeof(int));
    cudaMemsetAsync(stats, 0, 66 * sizeof(float));

    phase1<<<2 * GB + HB + NSB, 256>>>(image_feats, W_img, b_img,
                                       text_feats,  W_txt, b_txt,
                                       edge_u, edge_i, user_emb, item_emb);
    phase2<<<NBU + NBI + 1, 256>>>();
    phase3<<<2, 128>>>();
    phase4<<<NBU + NBI + APB, 256>>>(user_emb, item_emb);
    phase5<<<2048, 256>>>(edge_u, edge_i, val_ui, val_iu);
    phase6<<<SBU, 256>>>(o_imgU, o_txtU);
    phase7<<<SBI, 256>>>(o_imgI, o_txtI);
    phase8<<<SBU, 256>>>();
    phase9<<<SBI + SBU, 256>>>(o_imgU, o_txtU, o_u);
    phase10<<<SBI, 256>>>(o_imgI, o_txtI, o_i);
}

// round 14
// speedup vs baseline: 1.5410x; 1.0616x over previous
#include <cuda_runtime.h>
#include <cuda_fp16.h>
#include <math.h>
#include <stdint.h>

#define N_USERS 100000
#define N_ITEMS 50000
#define DD      64
#define NE      2000000
#define CAT_RATE 0.55f

#define NBU 98          // ceil(100000/1024)
#define NBI 49          // ceil(50000/1024)
#define GB  391         // ceil(50000/128) gemm blocks per matrix
#define SBU 12500       // 100000 rows / 8 warps
#define SBI 6250        // 50000 rows / 8 warps
#define APB 1024        // apply_norm grid-stride blocks
#define HB  2048        // hist blocks
#define NSB 1024        // norm_stats blocks
#define SCB 2048        // scatter-u blocks
#define SIB 1024        // scatter-i blocks (fused into P6)

// ------------------------- static device scratch (no allocs) -------------------------
// half2 tables for SpMM gathers (32 half2 = 64 halfs per row)
__device__ __half2 g_imgfeat_h[(size_t)N_ITEMS * 32];
__device__ __half2 g_txtfeat_h[(size_t)N_ITEMS * 32];
__device__ __half2 g_ug_h[(size_t)N_USERS * 32];
__device__ __half2 g_ig_h[(size_t)N_ITEMS * 32];
__device__ __half2 g_imgU_h[(size_t)N_USERS * 32];
__device__ __half2 g_txtU_h[(size_t)N_USERS * 32];
// fp32 accumulators
__device__ float g_uacc[(size_t)N_USERS * DD];
__device__ float g_iacc[(size_t)N_ITEMS * DD];

__device__ int   g_ucnt[N_USERS];
__device__ int   g_icnt[N_ITEMS];
__device__ int   g_urp[N_USERS + 1];
__device__ int   g_irp[N_ITEMS + 1];
__device__ int   g_ucur[N_USERS];
__device__ int   g_icur[N_ITEMS];
__device__ int2  g_uev[NE];     // packed (col, val-bits), user-CSR
__device__ int2  g_iev[NE];     // packed (col, val-bits), item-CSR
__device__ int   g_upart[128];
__device__ int   g_ipart[128];
__device__ float g_stats[66];   // [0..63] col means, [64] inv rownorm

// ======================= device role functions =======================

__device__ __forceinline__ void dev_hist(const int* __restrict__ eu,
                                         const int* __restrict__ ei,
                                         int bid, int nb) {
    int i = bid * 256 + threadIdx.x;
    int stride = nb * 256;
    for (; i < NE; i += stride) {
        atomicAdd(&g_ucnt[eu[i]], 1);
        atomicAdd(&g_icnt[ei[i]], 1);
    }
}

__device__ void dev_norm_stats(const float* __restrict__ ue,
                               const float* __restrict__ ie,
                               int bid, int nb) {
    int t = threadIdx.x;           // 256
    int c = t & 63;
    int rsub = t >> 6;             // 0..3
    float s = 0.f, q = 0.f;
    for (int r = bid * 4 + rsub; r < N_USERS + N_ITEMS; r += nb * 4) {
        const float* src = (r < N_USERS) ? (ue + (size_t)r * 64)
                                         : (ie + (size_t)(r - N_USERS) * 64);
        float v = src[c];
        s += v; q += v * v;
    }
    __shared__ float scol[256], sq[256];
    scol[t] = s; sq[t] = q;
    __syncthreads();
    for (int st = 128; st > 0; st >>= 1) { if (t < st) sq[t] += sq[t + st]; __syncthreads(); }
    if (t < 64) {
        float cs = scol[t] + scol[t + 64] + scol[t + 128] + scol[t + 192];
        atomicAdd(&g_stats[t], cs);
    }
    if (t == 0) atomicAdd(&g_stats[64], sq[0]);
}

// ---------------- tf32 tensor-core GEMM -> half2 output table -----------
__device__ __forceinline__ uint32_t f2tf32(float f) {
    uint32_t u;
    asm("cvt.rna.tf32.f32 %0, %1;" : "=r"(u) : "f"(f));
    return u;
}

#define WS_STRIDE 76    // floats per row (padded, float4-aligned, conflict-spread)

__device__ void dev_gemm_tf32(const float* __restrict__ A,
                              const float* __restrict__ W,
                              const float* __restrict__ bias,
                              __half2* __restrict__ out_h, int M, int K, int bid,
                              float* Ws /* [64*WS_STRIDE] smem */) {
    int tid  = threadIdx.x;
    int warp = tid >> 5, lane = tid & 31;
    int gid  = lane >> 2, tid4 = lane & 3;
    int rA = bid * 128 + warp * 16 + gid;
    int rB = rA + 8;
    bool okA = rA < M, okB = rB < M;
    const float* ArA = A + (size_t)rA * K;
    const float* ArB = A + (size_t)rB * K;

    float c[8][4];
    #pragma unroll
    for (int t = 0; t < 8; ++t) { c[t][0]=0.f; c[t][1]=0.f; c[t][2]=0.f; c[t][3]=0.f; }

    for (int k0 = 0; k0 < K; k0 += 64) {
        #pragma unroll
        for (int i = 0; i < 4; ++i) {
            int li = tid + i * 256;
            int r = li >> 4;
            int cb = (li & 15) * 4;
            float4 w = *(const float4*)(W + (size_t)(k0 + r) * 64 + cb);
            float* wr = Ws + r * WS_STRIDE;
            wr[((cb + 0) & 7) * 8 + ((cb + 0) >> 3)] = __uint_as_float(f2tf32(w.x));
            wr[((cb + 1) & 7) * 8 + ((cb + 1) >> 3)] = __uint_as_float(f2tf32(w.y));
            wr[((cb + 2) & 7) * 8 + ((cb + 2) >> 3)] = __uint_as_float(f2tf32(w.z));
            wr[((cb + 3) & 7) * 8 + ((cb + 3) >> 3)] = __uint_as_float(f2tf32(w.w));
        }
        __syncthreads();
        #pragma unroll
        for (int ks = 0; ks < 8; ++ks) {
            int kk = k0 + ks * 8;
            float a0 = 0.f, a1 = 0.f, a2 = 0.f, a3 = 0.f;
            if (okA) { a0 = ArA[kk + tid4]; a2 = ArA[kk + tid4 + 4]; }
            if (okB) { a1 = ArB[kk + tid4]; a3 = ArB[kk + tid4 + 4]; }
            uint32_t ua0 = f2tf32(a0), ua1 = f2tf32(a1);
            uint32_t ua2 = f2tf32(a2), ua3 = f2tf32(a3);
            const float* w0 = Ws + (ks * 8 + tid4) * WS_STRIDE + gid * 8;
            const float* w1 = Ws + (ks * 8 + tid4 + 4) * WS_STRIDE + gid * 8;
            float b0arr[8], b1arr[8];
            *(float4*)&b0arr[0] = *(const float4*)(w0);
            *(float4*)&b0arr[4] = *(const float4*)(w0 + 4);
            *(float4*)&b1arr[0] = *(const float4*)(w1);
            *(float4*)&b1arr[4] = *(const float4*)(w1 + 4);
            #pragma unroll
            for (int t = 0; t < 8; ++t) {
                uint32_t ub0 = __float_as_uint(b0arr[t]);
                uint32_t ub1 = __float_as_uint(b1arr[t]);
                asm volatile(
                    "mma.sync.aligned.m16n8k8.row.col.f32.tf32.tf32.f32 "
                    "{%0,%1,%2,%3}, {%4,%5,%6,%7}, {%8,%9}, {%0,%1,%2,%3};"
                    : "+f"(c[t][0]), "+f"(c[t][1]), "+f"(c[t][2]), "+f"(c[t][3])
                    : "r"(ua0), "r"(ua1), "r"(ua2), "r"(ua3), "r"(ub0), "r"(ub1));
            }
        }
        __syncthreads();
    }
    #pragma unroll
    for (int t = 0; t < 8; ++t) {
        int n = t * 8 + 2 * tid4;              // even
        float bx = bias[n], by = bias[n + 1];
        if (okA) out_h[(size_t)rA * 32 + (n >> 1)] = __floats2half2_rn(c[t][0] + bx, c[t][1] + by);
        if (okB) out_h[(size_t)rB * 32 + (n >> 1)] = __floats2half2_rn(c[t][2] + bx, c[t][3] + by);
    }
}

// ---------------- CSR scan helpers ----------------
__device__ void dev_block_sums(const int* __restrict__ cnt, int n,
                               int* __restrict__ part, int bid) {
    __shared__ int sm[256];
    int t = threadIdx.x;
    int base = bid * 1024;
    int s = 0;
    #pragma unroll
    for (int r = 0; r < 4; ++r) {
        int idx = base + t * 4 + r;
        if (idx < n) s += cnt[idx];
    }
    sm[t] = s; __syncthreads();
    for (int st = 128; st > 0; st >>= 1) { if (t < st) sm[t] += sm[t + st]; __syncthreads(); }
    if (t == 0) part[bid] = sm[0];
}

__device__ void dev_norm_finalize() {
    __shared__ float smf[64];
    int t = threadIdx.x;
    if (t < 64) {
        float n = (float)(N_USERS + N_ITEMS);
        float mean = g_stats[t] / n;
        smf[t] = mean * mean;
    }
    __syncthreads();
    if (t == 0) {
        float ssum = 0.f;
        #pragma unroll
        for (int i = 0; i < 64; ++i) ssum += smf[i];
        float n = (float)(N_USERS + N_ITEMS);
        float Q = g_stats[64];
        smf[0] = rsqrtf(Q / n - ssum + 1e-6f);
    }
    __syncthreads();
    if (t < 64) g_stats[t] = g_stats[t] / (float)(N_USERS + N_ITEMS);
    __syncthreads();
    if (t == 0) g_stats[64] = smf[0];
}

__device__ void dev_scan_small(int* __restrict__ part, int n) {
    __shared__ int sm[128];
    int t = threadIdx.x;
    int v = (t < n) ? part[t] : 0;
    sm[t] = v; __syncthreads();
    for (int off = 1; off < 128; off <<= 1) {
        int x = (t >= off) ? sm[t - off] : 0;
        __syncthreads();
        sm[t] += x;
        __syncthreads();
    }
    part[t] = sm[t] - v;   // exclusive
}

__device__ void dev_scan_chunks(const int* __restrict__ cnt, int n,
                                const int* __restrict__ part,
                                int* __restrict__ rp, int* __restrict__ cur, int bid) {
    __shared__ int sm[256];
    int t = threadIdx.x;
    int base = bid * 1024;
    int v[4]; int local = 0;
    #pragma unroll
    for (int r = 0; r < 4; ++r) {
        int idx = base + t * 4 + r;
        v[r] = (idx < n) ? cnt[idx] : 0;
        local += v[r];
    }
    sm[t] = local; __syncthreads();
    for (int off = 1; off < 256; off <<= 1) {
        int x = (t >= off) ? sm[t - off] : 0;
        __syncthreads();
        sm[t] += x;
        __syncthreads();
    }
    int excl = sm[t] - local + part[bid];
    #pragma unroll
    for (int r = 0; r < 4; ++r) {
        int idx = base + t * 4 + r;
        if (idx < n) { rp[idx] = excl; cur[idx] = excl; }
        excl += v[r];
    }
}

// normalize + write half tables and fp32 acc (pair-wise)
__device__ void dev_apply_norm(const float* __restrict__ ue,
                               const float* __restrict__ ie, int bid, int nb) {
    float inv = g_stats[64];
    int idx = bid * 256 + threadIdx.x;          // pair index
    int stride = nb * 256;
    const int NUp = N_USERS * 32;
    const int NTp = (N_USERS + N_ITEMS) * 32;
    for (; idx < NTp; idx += stride) {
        int p = idx & 31;                       // pair col
        float m0 = g_stats[2 * p], m1 = g_stats[2 * p + 1];
        if (idx < NUp) {
            float2 e = *(const float2*)(ue + (size_t)idx * 2);
            float v0 = (e.x - m0) * inv, v1 = (e.y - m1) * inv;
            g_ug_h[idx] = __floats2half2_rn(v0, v1);
            *(float2*)(g_uacc + (size_t)idx * 2) = make_float2(v0, v1);
        } else {
            int j = idx - NUp;
            float2 e = *(const float2*)(ie + (size_t)j * 2);
            float v0 = (e.x - m0) * inv, v1 = (e.y - m1) * inv;
            g_ig_h[j] = __floats2half2_rn(v0, v1);
            *(float2*)(g_iacc + (size_t)j * 2) = make_float2(v0, v1);
        }
    }
}

// scatter user-direction only: packed (col=item, val) into g_uev
__device__ void dev_scatter_u(const int* __restrict__ eu, const int* __restrict__ ei,
                              const float* __restrict__ vui, int bid, int nb) {
    int i = bid * 256 + threadIdx.x;
    int stride = nb * 256;
    for (; i < NE; i += stride) {
        int u = eu[i];
        int p = atomicAdd(&g_ucur[u], 1);
        g_uev[p] = make_int2(ei[i], __float_as_int(vui[i]));
    }
}

// scatter item-direction only: packed (col=user, val) into g_iev
__device__ void dev_scatter_i(const int* __restrict__ eu, const int* __restrict__ ei,
                              const float* __restrict__ viu, int bid, int nb) {
    int i = bid * 256 + threadIdx.x;
    int stride = nb * 256;
    for (; i < NE; i += stride) {
        int it = ei[i];
        int q = atomicAdd(&g_icur[it], 1);
        g_iev[q] = make_int2(eu[i], __float_as_int(viu[i]));
    }
}

// ---------------- half-gather SpMM (warp/row, lane = 1 half2, 2-edge unroll, packed ev) ----
__device__ __forceinline__ void dev_spmm_h(const int* __restrict__ rp,
                                           const int2* __restrict__ evs,
                                           const __half2* __restrict__ src,
                                           __half2* __restrict__ out_h,
                                           float* __restrict__ acc,
                                           int n_rows, int bid) {
    int row = bid * 8 + ((int)threadIdx.x >> 5);
    if (row >= n_rows) return;
    int lane = threadIdx.x & 31;
    int s = rp[row], e = rp[row + 1];
    float ax = 0.f, ay = 0.f;
    int j = s;
    for (; j + 2 <= e; j += 2) {
        int2 e0 = __ldg(&evs[j]);
        int2 e1 = __ldg(&evs[j + 1]);
        float v0 = __int_as_float(e0.y);
        float v1 = __int_as_float(e1.y);
        float2 s0 = __half22float2(src[(size_t)e0.x * 32 + lane]);
        float2 s1 = __half22float2(src[(size_t)e1.x * 32 + lane]);
        ax = fmaf(v0, s0.x, ax); ay = fmaf(v0, s0.y, ay);
        ax = fmaf(v1, s1.x, ax); ay = fmaf(v1, s1.y, ay);
    }
    if (j < e) {
        int2 e0 = __ldg(&evs[j]);
        float v = __int_as_float(e0.y);
        float2 sv = __half22float2(src[(size_t)e0.x * 32 + lane]);
        ax = fmaf(v, sv.x, ax); ay = fmaf(v, sv.y, ay);
    }
    size_t base = (size_t)row * 32 + lane;
    if (out_h) out_h[base] = __floats2half2_rn(ax, ay);
    if (acc) {
        float2* ap = (float2*)(acc + base * 2);
        float2 t = *ap;
        t.x += ax; t.y += ay;
        *ap = t;
    }
}

// triple-source half gather; fp32 outputs for A/B (+ optional half copies), half C + fp32 acc
__device__ __forceinline__ void dev_spmm3_h(const int* __restrict__ rp,
                                            const int2* __restrict__ evs,
                                            const __half2* __restrict__ sA,
                                            const __half2* __restrict__ sB,
                                            const __half2* __restrict__ sC,
                                            float* __restrict__ oA32,
                                            float* __restrict__ oB32,
                                            __half2* __restrict__ oAh,
                                            __half2* __restrict__ oBh,
                                            __half2* __restrict__ oCh,
                                            float* __restrict__ acc,
                                            int n_rows, int bid) {
    int row = bid * 8 + ((int)threadIdx.x >> 5);
    if (row >= n_rows) return;
    int lane = threadIdx.x & 31;
    int s = rp[row], e = rp[row + 1];
    float aAx=0.f, aAy=0.f, aBx=0.f, aBy=0.f, aCx=0.f, aCy=0.f;
    int j = s;
    for (; j + 2 <= e; j += 2) {
        int2 e0 = __ldg(&evs[j]);
        int2 e1 = __ldg(&evs[j + 1]);
        float v0 = __int_as_float(e0.y);
        float v1 = __int_as_float(e1.y);
        size_t o0 = (size_t)e0.x * 32 + lane;
        size_t o1 = (size_t)e1.x * 32 + lane;
        float2 a0 = __half22float2(sA[o0]);
        float2 b0 = __half22float2(sB[o0]);
        float2 d0 = __half22float2(sC[o0]);
        float2 a1 = __half22float2(sA[o1]);
        float2 b1 = __half22float2(sB[o1]);
        float2 d1 = __half22float2(sC[o1]);
        aAx = fmaf(v0, a0.x, aAx); aAy = fmaf(v0, a0.y, aAy);
        aBx = fmaf(v0, b0.x, aBx); aBy = fmaf(v0, b0.y, aBy);
        aCx = fmaf(v0, d0.x, aCx); aCy = fmaf(v0, d0.y, aCy);
        aAx = fmaf(v1, a1.x, aAx); aAy = fmaf(v1, a1.y, aAy);
        aBx = fmaf(v1, b1.x, aBx); aBy = fmaf(v1, b1.y, aBy);
        aCx = fmaf(v1, d1.x, aCx); aCy = fmaf(v1, d1.y, aCy);
    }
    if (j < e) {
        int2 e0 = __ldg(&evs[j]);
        float v = __int_as_float(e0.y);
        size_t o = (size_t)e0.x * 32 + lane;
        float2 a = __half22float2(sA[o]);
        float2 b = __half22float2(sB[o]);
        float2 d = __half22float2(sC[o]);
        aAx = fmaf(v, a.x, aAx); aAy = fmaf(v, a.y, aAy);
        aBx = fmaf(v, b.x, aBx); aBy = fmaf(v, b.y, aBy);
        aCx = fmaf(v, d.x, aCx); aCy = fmaf(v, d.y, aCy);
    }
    size_t base = (size_t)row * 32 + lane;
    *(float2*)(oA32 + base * 2) = make_float2(aAx, aAy);
    *(float2*)(oB32 + base * 2) = make_float2(aBx, aBy);
    if (oAh) oAh[base] = __floats2half2_rn(aAx, aAy);
    if (oBh) oBh[base] = __floats2half2_rn(aBx, aBy);
    oCh[base] = __floats2half2_rn(aCx, aCy);
    float2* ap = (float2*)(acc + base * 2);
    float2 t = *ap;
    t.x += aCx; t.y += aCy;
    *ap = t;
}

__device__ __forceinline__ void dev_finalize(const float* __restrict__ acc,
                                             const float* __restrict__ A,
                                             const float* __restrict__ B,
                                             float* __restrict__ out, int n, int bid) {
    int row = bid * 8 + ((int)threadIdx.x >> 5);
    if (row >= n) return;
    int lane = threadIdx.x & 31;
    size_t base = (size_t)row * 64 + lane * 2;
    float2 a = *(const float2*)(A + base);
    float2 b = *(const float2*)(B + base);
    float2 ac = *(const float2*)(acc + base);
    float sa = a.x * a.x + a.y * a.y;
    float sb = b.x * b.x + b.y * b.y;
    #pragma unroll
    for (int o = 16; o; o >>= 1) {
        sa += __shfl_xor_sync(0xFFFFFFFFu, sa, o);
        sb += __shfl_xor_sync(0xFFFFFFFFu, sb, o);
    }
    float ka = CAT_RATE / fmaxf(sqrtf(sa), 1e-12f);
    float kb = CAT_RATE / fmaxf(sqrtf(sb), 1e-12f);
    const float inv_layers = 1.0f / 3.0f;
    float2 o2 = make_float2(ac.x * inv_layers + ka * a.x + kb * b.x,
                            ac.y * inv_layers + ka * a.y + kb * b.y);
    *(float2*)(out + base) = o2;
}

// ======================= phase kernels =======================

// P1: gemm-img || gemm-txt || hist || norm_stats
__global__ __launch_bounds__(256) void phase1(const float* __restrict__ imgF,
                                              const float* __restrict__ Wi,
                                              const float* __restrict__ bi,
                                              const float* __restrict__ txtF,
                                              const float* __restrict__ Wt,
                                              const float* __restrict__ bt,
                                              const int* __restrict__ eu,
                                              const int* __restrict__ ei,
                                              const float* __restrict__ ue,
                                              const float* __restrict__ ie) {
    __shared__ float Ws[64 * WS_STRIDE];
    int b = blockIdx.x;
    if (b < GB)               dev_gemm_tf32(imgF, Wi, bi, g_imgfeat_h, N_ITEMS, 1024, b, Ws);
    else if (b < 2 * GB)      dev_gemm_tf32(txtF, Wt, bt, g_txtfeat_h, N_ITEMS, 384, b - GB, Ws);
    else if (b < 2 * GB + HB) dev_hist(eu, ei, b - 2 * GB, HB);
    else                      dev_norm_stats(ue, ie, b - 2 * GB - HB, NSB);
}

// P2: block_sums u || block_sums i || norm_finalize
__global__ __launch_bounds__(256) void phase2() {
    int b = blockIdx.x;
    if (b < NBU)            dev_block_sums(g_ucnt, N_USERS, g_upart, b);
    else if (b < NBU + NBI) dev_block_sums(g_icnt, N_ITEMS, g_ipart, b - NBU);
    else                    dev_norm_finalize();
}

// P3: small scans + tails
__global__ __launch_bounds__(128) void phase3() {
    if (blockIdx.x == 0) {
        dev_scan_small(g_upart, NBU);
        if (threadIdx.x == 0) { g_urp[N_USERS] = NE; g_irp[N_ITEMS] = NE; }
    } else {
        dev_scan_small(g_ipart, NBI);
    }
}

// P4: scan_chunks u/i || apply_norm
__global__ __launch_bounds__(256) void phase4(const float* __restrict__ ue,
                                              const float* __restrict__ ie) {
    int b = blockIdx.x;
    if (b < NBU)            dev_scan_chunks(g_ucnt, N_USERS, g_upart, g_urp, g_ucur, b);
    else if (b < NBU + NBI) dev_scan_chunks(g_icnt, N_ITEMS, g_ipart, g_irp, g_icur, b - NBU);
    else                    dev_apply_norm(ue, ie, b - NBU - NBI, APB);
}

// P5: scatter-u only
__global__ __launch_bounds__(256) void phase5(const int* __restrict__ eu,
                                              const int* __restrict__ ei,
                                              const float* __restrict__ vui) {
    dev_scatter_u(eu, ei, vui, blockIdx.x, gridDim.x);
}

// P6: triple-U || scatter-i (hidden under the SpMM)
__global__ __launch_bounds__(256) void phase6(float* __restrict__ o_imgU,
                                              float* __restrict__ o_txtU,
                                              const int* __restrict__ eu,
                                              const int* __restrict__ ei,
                                              const float* __restrict__ viu) {
    int b = blockIdx.x;
    if (b < SBU)
        dev_spmm3_h(g_urp, g_uev, g_imgfeat_h, g_txtfeat_h, g_ig_h,
                    o_imgU, o_txtU, g_imgU_h, g_txtU_h, g_ug_h, g_uacc,
                    N_USERS, b);
    else
        dev_scatter_i(eu, ei, viu, b - SBU, SIB);
}

// P7: triple-I
__global__ __launch_bounds__(256) void phase7(float* __restrict__ o_imgI,
                                              float* __restrict__ o_txtI) {
    dev_spmm3_h(g_irp, g_iev, g_imgU_h, g_txtU_h, g_ug_h,
                o_imgI, o_txtI, (__half2*)0, (__half2*)0, g_ig_h, g_iacc,
                N_ITEMS, blockIdx.x);
}

// P8: GNN layer-2 user spmm
__global__ __launch_bounds__(256) void phase8() {
    dev_spmm_h(g_urp, g_uev, g_ig_h, g_ug_h, g_uacc, N_USERS, blockIdx.x);
}

// P9: GNN layer-2 item spmm (acc only) || finalize users
__global__ __launch_bounds__(256) void phase9(const float* __restrict__ o_imgU,
                                              const float* __restrict__ o_txtU,
                                              float* __restrict__ o_u) {
    int b = blockIdx.x;
    if (b < SBI) dev_spmm_h(g_irp, g_iev, g_ug_h, (__half2*)0, g_iacc, N_ITEMS, b);
    else         dev_finalize(g_uacc, o_imgU, o_txtU, o_u, N_USERS, b - SBI);
}

// P10: finalize items
__global__ __launch_bounds__(256) void phase10(const float* __restrict__ o_imgI,
                                               const float* __restrict__ o_txtI,
                                               float* __restrict__ o_i) {
    dev_finalize(g_iacc, o_imgI, o_txtI, o_i, N_ITEMS, blockIdx.x);
}

// ======================= launch =======================
extern "C" void kernel_launch(void* const* d_in, const int* in_sizes, int n_in,
                              void* d_out, int out_size) {
    const float* image_feats = (const float*)d_in[0];
    const float* text_feats  = (const float*)d_in[1];
    const float* user_emb    = (const float*)d_in[2];
    const float* item_emb    = (const float*)d_in[3];
    const float* W_img       = (const float*)d_in[4];
    const float* b_img       = (const float*)d_in[5];
    const float* W_txt       = (const float*)d_in[6];
    const float* b_txt       = (const float*)d_in[7];
    const float* val_ui      = (const float*)d_in[8];
    const float* val_iu      = (const float*)d_in[9];
    const int*   edge_u      = (const int*)d_in[10];
    const int*   edge_i      = (const int*)d_in[11];

    float* out = (float*)d_out;
    float* o_u    = out;                      // 100000*64
    float* o_i    = out + 6400000;            // 50000*64
    float* o_imgI = out + 9600000;            // 50000*64
    float* o_txtI = out + 12800000;           // 50000*64
    float* o_imgU = out + 16000000;           // 100000*64
    float* o_txtU = out + 22400000;           // 100000*64

    void *p;
    int *ucnt, *icnt; float *stats;
    cudaGetSymbolAddress(&p, g_ucnt);  ucnt  = (int*)p;
    cudaGetSymbolAddress(&p, g_icnt);  icnt  = (int*)p;
    cudaGetSymbolAddress(&p, g_stats); stats = (float*)p;

    cudaMemsetAsync(ucnt, 0, N_USERS * sizeof(int));
    cudaMemsetAsync(icnt, 0, N_ITEMS * sizeof(int));
    cudaMemsetAsync(stats, 0, 66 * sizeof(float));

    phase1<<<2 * GB + HB + NSB, 256>>>(image_feats, W_img, b_img,
                                       text_feats,  W_txt, b_txt,
                                       edge_u, edge_i, user_emb, item_emb);
    phase2<<<NBU + NBI + 1, 256>>>();
    phase3<<<2, 128>>>();
    phase4<<<NBU + NBI + APB, 256>>>(user_emb, item_emb);
    phase5<<<SCB, 256>>>(edge_u, edge_i, val_ui);
    phase6<<<SBU + SIB, 256>>>(o_imgU, o_txtU, edge_u, edge_i, val_iu);
    phase7<<<SBI, 256>>>(o_imgI, o_txtI);
    phase8<<<SBU, 256>>>();
    phase9<<<SBI + SBU, 256>>>(o_imgU, o_txtU, o_u);
    phase10<<<SBI, 256>>>(o_imgI, o_txtI, o_i);
}